// round 3
// baseline (speedup 1.0000x reference)
#include <cuda_runtime.h>
#include <math.h>
#include <stdint.h>

// Problem constants (fixed by reference setup)
#define TT   8192      // total tokens B*S
#define DD   2048      // d_model
#define HH   16        // heads
#define DHE  128       // head dim
#define BBQ  8         // batch
#define SS   1024      // seq len
#define PBS  256       // page block size
#define NBLK 64        // physical blocks

typedef unsigned long long ull;

// Scratch (static device arrays: allocation-free rule)
__device__ float g_q[(size_t)TT * DD];
__device__ float g_k[(size_t)TT * DD];
__device__ float g_v[(size_t)TT * DD];
__device__ float g_attn[(size_t)TT * DD];

// ---------- f32x2 packed helpers ----------
__device__ __forceinline__ void fma2(ull &acc, ull a, ull b) {
    asm volatile("fma.rn.f32x2 %0, %1, %2, %0;" : "+l"(acc) : "l"(a), "l"(b));
}
__device__ __forceinline__ ull pack2(float lo, float hi) {
    ull r; asm("mov.b64 %0, {%1, %2};" : "=l"(r) : "f"(lo), "f"(hi)); return r;
}
__device__ __forceinline__ ull mul2(ull a, ull b) {
    ull r; asm("mul.rn.f32x2 %0, %1, %2;" : "=l"(r) : "l"(a), "l"(b)); return r;
}
__device__ __forceinline__ float lo2(ull v) { return __uint_as_float((unsigned)v); }
__device__ __forceinline__ float hi2(ull v) { return __uint_as_float((unsigned)(v >> 32)); }

// ============================================================
// GEMM (NT): C[M,N] = A[M,K] * B[N,K]^T   M=8192, N=K=2048
// 128x128 tile, BK=16, 256 threads, 8x8 micro via fma.rn.f32x2.
// A tile stored in smem as duplicated f32x2 pairs -> inner loop has
// zero pack instructions: only LDS.128 + FMA2.
// ============================================================
#define BM 128
#define BN 128
#define BK 16
#define AST 132   // ull stride for As2 row
#define BST 132   // float stride for Bs row

__global__ __launch_bounds__(256, 2)
void gemm_nt(const float* __restrict__ A, const float* __restrict__ B,
             float* __restrict__ C) {
    const int M = TT, N = DD, K = DD; (void)M;
    __shared__ __align__(16) ull   As2[BK * AST];
    __shared__ __align__(16) float Bs [BK * BST];

    int tid  = threadIdx.x;
    int m0   = blockIdx.y * BM;
    int n0   = blockIdx.x * BN;
    int row0 = (tid >> 4) * 8;
    int col0 = (tid & 15) * 8;

    // load-item mapping: item i in [0,512): r=i>>2, c4=i&3 (float4 along K)
    int r1  = tid >> 2;
    int c41 = tid & 3;

    const float* Ap1 = A + (size_t)(m0 + r1)      * K + c41 * 4;
    const float* Ap2 = A + (size_t)(m0 + r1 + 64) * K + c41 * 4;
    const float* Bp1 = B + (size_t)(n0 + r1)      * K + c41 * 4;
    const float* Bp2 = B + (size_t)(n0 + r1 + 64) * K + c41 * 4;

    ull acc[8][4];
#pragma unroll
    for (int i = 0; i < 8; i++)
#pragma unroll
        for (int j = 0; j < 4; j++) acc[i][j] = 0ull;

    const int nk = K / BK;  // 128
    float4 pa1 = *(const float4*)(Ap1);
    float4 pa2 = *(const float4*)(Ap2);
    float4 pb1 = *(const float4*)(Bp1);
    float4 pb2 = *(const float4*)(Bp2);

    for (int kt = 0; kt < nk; kt++) {
        __syncthreads();
        {
            int cb = c41 * 4;
            As2[(cb + 0) * AST + r1]      = pack2(pa1.x, pa1.x);
            As2[(cb + 1) * AST + r1]      = pack2(pa1.y, pa1.y);
            As2[(cb + 2) * AST + r1]      = pack2(pa1.z, pa1.z);
            As2[(cb + 3) * AST + r1]      = pack2(pa1.w, pa1.w);
            As2[(cb + 0) * AST + r1 + 64] = pack2(pa2.x, pa2.x);
            As2[(cb + 1) * AST + r1 + 64] = pack2(pa2.y, pa2.y);
            As2[(cb + 2) * AST + r1 + 64] = pack2(pa2.z, pa2.z);
            As2[(cb + 3) * AST + r1 + 64] = pack2(pa2.w, pa2.w);
            Bs [(cb + 0) * BST + r1]      = pb1.x;
            Bs [(cb + 1) * BST + r1]      = pb1.y;
            Bs [(cb + 2) * BST + r1]      = pb1.z;
            Bs [(cb + 3) * BST + r1]      = pb1.w;
            Bs [(cb + 0) * BST + r1 + 64] = pb2.x;
            Bs [(cb + 1) * BST + r1 + 64] = pb2.y;
            Bs [(cb + 2) * BST + r1 + 64] = pb2.z;
            Bs [(cb + 3) * BST + r1 + 64] = pb2.w;
        }
        __syncthreads();
        if (kt + 1 < nk) {
            int ko = (kt + 1) * BK;
            pa1 = *(const float4*)(Ap1 + ko);
            pa2 = *(const float4*)(Ap2 + ko);
            pb1 = *(const float4*)(Bp1 + ko);
            pb2 = *(const float4*)(Bp2 + ko);
        }
#pragma unroll
        for (int kk = 0; kk < BK; kk++) {
            ulonglong2 a01 = *(const ulonglong2*)(As2 + kk * AST + row0);
            ulonglong2 a23 = *(const ulonglong2*)(As2 + kk * AST + row0 + 2);
            ulonglong2 a45 = *(const ulonglong2*)(As2 + kk * AST + row0 + 4);
            ulonglong2 a67 = *(const ulonglong2*)(As2 + kk * AST + row0 + 6);
            ulonglong2 b01 = *(const ulonglong2*)(Bs  + kk * BST + col0);
            ulonglong2 b23 = *(const ulonglong2*)(Bs  + kk * BST + col0 + 4);
            ull a[8] = {a01.x, a01.y, a23.x, a23.y, a45.x, a45.y, a67.x, a67.y};
            ull b[4] = {b01.x, b01.y, b23.x, b23.y};
#pragma unroll
            for (int i = 0; i < 8; i++)
#pragma unroll
                for (int j = 0; j < 4; j++) fma2(acc[i][j], a[i], b[j]);
        }
    }

#pragma unroll
    for (int i = 0; i < 8; i++) {
        float4 o0 = make_float4(lo2(acc[i][0]), hi2(acc[i][0]),
                                lo2(acc[i][1]), hi2(acc[i][1]));
        float4 o1 = make_float4(lo2(acc[i][2]), hi2(acc[i][2]),
                                lo2(acc[i][3]), hi2(acc[i][3]));
        float* cp = C + (size_t)(m0 + row0 + i) * N + n0 + col0;
        *(float4*)(cp)     = o0;
        *(float4*)(cp + 4) = o1;
    }
}

// ============================================================
// RoPE on q and k (in place). inv_freq computed in double for
// angle accuracy (pos up to 1023 multiplies the rounding error).
// ============================================================
__global__ void rope_kernel(float* __restrict__ q, float* __restrict__ k) {
    int idx = blockIdx.x * blockDim.x + threadIdx.x;
    if (idx >= TT * HH * (DHE / 2)) return;
    int j  = idx & 63;
    int th = idx >> 6;
    int h  = th & (HH - 1);
    int t  = th >> 4;
    int pos = t & (SS - 1);

    // inv_freq = 10000^(-j/64) = 2^(-j * log2(10000)/64)
    double inv = exp2(-(double)j * 0.20762050593046014);
    float ang  = (float)((double)pos * inv);
    float sn, cs;
    sincosf(ang, &sn, &cs);

    size_t base = (size_t)t * DD + h * DHE + j;
    float q0 = q[base], q1 = q[base + 64];
    q[base]      = q0 * cs - q1 * sn;
    q[base + 64] = q1 * cs + q0 * sn;
    float k0 = k[base], k1 = k[base + 64];
    k[base]      = k0 * cs - k1 * sn;
    k[base + 64] = k1 * cs + k0 * sn;
}

// ============================================================
// Paged KV scatter: one block per token copies its k,v rows
// ============================================================
__global__ void scatter_kv(const float* __restrict__ k, const float* __restrict__ v,
                           const int* __restrict__ block_table, float* __restrict__ cache) {
    int t   = blockIdx.x;
    int pos = t & (SS - 1);
    int seq = t >> 10;
    int phys = block_table[seq * (SS / PBS) + (pos / PBS)];
    int off  = pos & (PBS - 1);

    for (int i = threadIdx.x; i < 2 * DD / 4; i += blockDim.x) {  // 1024 float4
        int kv  = i >> 9;
        int rem = i & 511;
        int hh  = rem >> 5;
        int d4  = rem & 31;
        const float* src = kv ? v : k;
        float4 val = *(const float4*)(src + (size_t)t * DD + hh * DHE + d4 * 4);
        size_t dst = ((((size_t)phys * 2 + kv) * HH + hh) * PBS + off) * DHE + d4 * 4;
        *(float4*)(cache + dst) = val;
    }
}

// ============================================================
// Flash attention, causal, fp32 with f32x2 packed math.
// Block = (qt, h, b): 64 queries x all K-tiles <= qt.
// ============================================================
#define QTS  64
#define QSTR 132
#define PSTR 65
#define QK_SCALE 0.08838834764831843f   // 1/sqrt(128)

__global__ __launch_bounds__(256)
void attn_kernel(const float* __restrict__ q, const float* __restrict__ kg,
                 const float* __restrict__ vg, float* __restrict__ o) {
    extern __shared__ __align__(16) float sm[];
    float* Qs  = sm;                    // QTS*QSTR
    float* KVs = Qs + QTS * QSTR;       // QTS*QSTR (K then reused for V)
    float* Ps  = KVs + QTS * QSTR;      // QTS*PSTR

    int qt = blockIdx.x, h = blockIdx.y, b = blockIdx.z;
    int tid = threadIdx.x;
    int ty = tid >> 4, tx = tid & 15;
    int r0 = ty * 4, c0 = tx * 4, d0 = tx * 8;
    int qbase = b * SS + qt * QTS;

    // load Q tile (pre-scaled)
    for (int i = tid; i < QTS * DHE / 4; i += 256) {
        int r = i >> 5, c4 = i & 31;
        float4 val = *(const float4*)(q + (size_t)(qbase + r) * DD + h * DHE + c4 * 4);
        val.x *= QK_SCALE; val.y *= QK_SCALE; val.z *= QK_SCALE; val.w *= QK_SCALE;
        *(float4*)(Qs + r * QSTR + c4 * 4) = val;
    }

    float m_i[4], l_i[4];
    ull O2[4][4];
#pragma unroll
    for (int i = 0; i < 4; i++) {
        m_i[i] = -INFINITY; l_i[i] = 0.f;
#pragma unroll
        for (int j = 0; j < 4; j++) O2[i][j] = 0ull;
    }

    for (int kt = 0; kt <= qt; kt++) {
        __syncthreads();   // prior PV readers of KVs done
        int kbase = b * SS + kt * QTS;
        for (int i = tid; i < QTS * DHE / 4; i += 256) {
            int r = i >> 5, c4 = i & 31;
            *(float4*)(KVs + r * QSTR + c4 * 4) =
                *(const float4*)(kg + (size_t)(kbase + r) * DD + h * DHE + c4 * 4);
        }
        __syncthreads();

        // scores: acc over d-pairs via f32x2
        ull acc[4][4];
#pragma unroll
        for (int i = 0; i < 4; i++)
#pragma unroll
            for (int j = 0; j < 4; j++) acc[i][j] = 0ull;

#pragma unroll 4
        for (int d = 0; d < DHE; d += 2) {
            ull a0 = *(const ull*)(Qs + (r0 + 0) * QSTR + d);
            ull a1 = *(const ull*)(Qs + (r0 + 1) * QSTR + d);
            ull a2 = *(const ull*)(Qs + (r0 + 2) * QSTR + d);
            ull a3 = *(const ull*)(Qs + (r0 + 3) * QSTR + d);
            ull b0 = *(const ull*)(KVs + (c0 + 0) * QSTR + d);
            ull b1 = *(const ull*)(KVs + (c0 + 1) * QSTR + d);
            ull b2 = *(const ull*)(KVs + (c0 + 2) * QSTR + d);
            ull b3 = *(const ull*)(KVs + (c0 + 3) * QSTR + d);
            fma2(acc[0][0], a0, b0); fma2(acc[0][1], a0, b1);
            fma2(acc[0][2], a0, b2); fma2(acc[0][3], a0, b3);
            fma2(acc[1][0], a1, b0); fma2(acc[1][1], a1, b1);
            fma2(acc[1][2], a1, b2); fma2(acc[1][3], a1, b3);
            fma2(acc[2][0], a2, b0); fma2(acc[2][1], a2, b1);
            fma2(acc[2][2], a2, b2); fma2(acc[2][3], a2, b3);
            fma2(acc[3][0], a3, b0); fma2(acc[3][1], a3, b1);
            fma2(acc[3][2], a3, b2); fma2(acc[3][3], a3, b3);
        }

        float s[4][4];
#pragma unroll
        for (int i = 0; i < 4; i++)
#pragma unroll
            for (int j = 0; j < 4; j++)
                s[i][j] = lo2(acc[i][j]) + hi2(acc[i][j]);

        if (kt == qt) {
#pragma unroll
            for (int i = 0; i < 4; i++)
#pragma unroll
                for (int j = 0; j < 4; j++)
                    if (c0 + j > r0 + i) s[i][j] = -INFINITY;
        }

#pragma unroll
        for (int i = 0; i < 4; i++) {
            float mx = fmaxf(fmaxf(s[i][0], s[i][1]), fmaxf(s[i][2], s[i][3]));
#pragma unroll
            for (int msk = 8; msk >= 1; msk >>= 1)
                mx = fmaxf(mx, __shfl_xor_sync(0xffffffffu, mx, msk));
            float mn = fmaxf(m_i[i], mx);
            float p0 = __expf(s[i][0] - mn);
            float p1 = __expf(s[i][1] - mn);
            float p2 = __expf(s[i][2] - mn);
            float p3 = __expf(s[i][3] - mn);
            float sum = p0 + p1 + p2 + p3;
#pragma unroll
            for (int msk = 8; msk >= 1; msk >>= 1)
                sum += __shfl_xor_sync(0xffffffffu, sum, msk);
            float al = __expf(m_i[i] - mn);
            l_i[i] = l_i[i] * al + sum;
            m_i[i] = mn;
            ull al2 = pack2(al, al);
#pragma unroll
            for (int j = 0; j < 4; j++) O2[i][j] = mul2(O2[i][j], al2);
            float* pr = Ps + (r0 + i) * PSTR + c0;
            pr[0] = p0; pr[1] = p1; pr[2] = p2; pr[3] = p3;
        }
        __syncthreads();   // Ps visible + K-readers done before V overwrite

        // load V tile into KVs
        for (int i = tid; i < QTS * DHE / 4; i += 256) {
            int r = i >> 5, c4 = i & 31;
            *(float4*)(KVs + r * QSTR + c4 * 4) =
                *(const float4*)(vg + (size_t)(kbase + r) * DD + h * DHE + c4 * 4);
        }
        __syncthreads();

        // O += P @ V  (f32x2 over dim-pairs)
#pragma unroll 2
        for (int c = 0; c < QTS; c++) {
            ull v0 = *(const ull*)(KVs + c * QSTR + d0);
            ull v1 = *(const ull*)(KVs + c * QSTR + d0 + 2);
            ull v2 = *(const ull*)(KVs + c * QSTR + d0 + 4);
            ull v3 = *(const ull*)(KVs + c * QSTR + d0 + 6);
#pragma unroll
            for (int i = 0; i < 4; i++) {
                float p = Ps[(r0 + i) * PSTR + c];
                ull pp = pack2(p, p);
                fma2(O2[i][0], pp, v0);
                fma2(O2[i][1], pp, v1);
                fma2(O2[i][2], pp, v2);
                fma2(O2[i][3], pp, v3);
            }
        }
    }

    // normalize and write out
#pragma unroll
    for (int i = 0; i < 4; i++) {
        float inv = 1.f / l_i[i];
        float4 o0 = make_float4(lo2(O2[i][0]) * inv, hi2(O2[i][0]) * inv,
                                lo2(O2[i][1]) * inv, hi2(O2[i][1]) * inv);
        float4 o1 = make_float4(lo2(O2[i][2]) * inv, hi2(O2[i][2]) * inv,
                                lo2(O2[i][3]) * inv, hi2(O2[i][3]) * inv);
        float* op = o + (size_t)(qbase + r0 + i) * DD + h * DHE + d0;
        *(float4*)(op)     = o0;
        *(float4*)(op + 4) = o1;
    }
}

// ============================================================
// Launch
// ============================================================
extern "C" void kernel_launch(void* const* d_in, const int* in_sizes, int n_in,
                              void* d_out, int out_size) {
    (void)in_sizes; (void)n_in; (void)out_size;
    const float* x      = (const float*)d_in[0];
    const float* Wq     = (const float*)d_in[1];
    const float* Wk     = (const float*)d_in[2];
    const float* Wv     = (const float*)d_in[3];
    const float* Wo     = (const float*)d_in[4];
    const float* kv_in  = (const float*)d_in[5];
    const int*   btab   = (const int*)d_in[7];

    float* out       = (float*)d_out;
    float* cache_out = out + (size_t)TT * DD;

    void* p;
    cudaGetSymbolAddress(&p, g_q);    float* gq = (float*)p;
    cudaGetSymbolAddress(&p, g_k);    float* gk = (float*)p;
    cudaGetSymbolAddress(&p, g_v);    float* gv = (float*)p;
    cudaGetSymbolAddress(&p, g_attn); float* ga = (float*)p;

    // copy input cache (untouched blocks must survive), then scatter overwrites
    cudaMemcpyAsync(cache_out, kv_in,
                    (size_t)NBLK * 2 * HH * PBS * DHE * sizeof(float),
                    cudaMemcpyDeviceToDevice, 0);

    dim3 ggrid(DD / BN, TT / BM);   // (16, 64)
    gemm_nt<<<ggrid, 256>>>(x, Wq, gq);
    gemm_nt<<<ggrid, 256>>>(x, Wk, gk);
    gemm_nt<<<ggrid, 256>>>(x, Wv, gv);

    int nrope = TT * HH * (DHE / 2);
    rope_kernel<<<(nrope + 255) / 256, 256>>>(gq, gk);

    scatter_kv<<<TT, 256>>>(gk, gv, btab, cache_out);

    size_t smem = (size_t)(QTS * QSTR * 2 + QTS * PSTR) * sizeof(float);
    cudaFuncSetAttribute(attn_kernel, cudaFuncAttributeMaxDynamicSharedMemorySize, (int)smem);
    attn_kernel<<<dim3(SS / QTS, HH, BBQ), 256, smem>>>(gq, gk, gv, ga);

    gemm_nt<<<ggrid, 256>>>(ga, Wo, out);
}

// round 10
// speedup vs baseline: 1.9002x; 1.9002x over previous
#include <cuda_runtime.h>
#include <cuda_bf16.h>
#include <math.h>
#include <stdint.h>

// Problem constants (fixed by reference setup)
#define TT   8192      // total tokens B*S
#define DD   2048      // d_model
#define HH   16        // heads
#define DHE  128       // head dim
#define BBQ  8         // batch
#define SS   1024      // seq len
#define PBS  256       // page block size
#define NBLK 64        // physical blocks

typedef unsigned long long ull;

// Scratch (static device arrays: allocation-free rule)
__device__ float g_q[(size_t)TT * DD];
__device__ float g_k[(size_t)TT * DD];
__device__ float g_v[(size_t)TT * DD];
__device__ float g_attn[(size_t)TT * DD];
__device__ __nv_bfloat16 g_ah[(size_t)TT * DD];   // A hi split (x, then attn out)
__device__ __nv_bfloat16 g_al[(size_t)TT * DD];   // A lo split
__device__ __nv_bfloat16 g_bh[(size_t)DD * DD];   // W hi split (reused per GEMM)
__device__ __nv_bfloat16 g_bl[(size_t)DD * DD];   // W lo split
__device__ float2 g_ropetab[SS * 64];             // cos/sin table

// ---------- helpers ----------
__device__ __forceinline__ uint32_t smem_to_u32(const void* smem_ptr) {
    uint32_t addr;
    asm("{ .reg .u64 tmp; cvta.to.shared.u64 tmp, %1; cvt.u32.u64 %0, tmp; }"
        : "=r"(addr) : "l"(smem_ptr));
    return addr;
}
__device__ __forceinline__ void cpa16(uint32_t dst, const void* src) {
    asm volatile("cp.async.cg.shared.global [%0], [%1], 16;" :: "r"(dst), "l"(src));
}
#define CP_COMMIT() asm volatile("cp.async.commit_group;" ::: "memory")
#define CP_WAIT(n)  asm volatile("cp.async.wait_group %0;" :: "n"(n) : "memory")

__device__ __forceinline__ void ldsm4(uint32_t &r0, uint32_t &r1, uint32_t &r2,
                                      uint32_t &r3, uint32_t addr) {
    asm volatile("ldmatrix.sync.aligned.m8n8.x4.shared.b16 {%0,%1,%2,%3}, [%4];"
        : "=r"(r0), "=r"(r1), "=r"(r2), "=r"(r3) : "r"(addr));
}
__device__ __forceinline__ void mma16816(float* d, const uint32_t* a, const uint32_t* b) {
    asm volatile(
        "mma.sync.aligned.m16n8k16.row.col.f32.bf16.bf16.f32 "
        "{%0,%1,%2,%3}, {%4,%5,%6,%7}, {%8,%9}, {%0,%1,%2,%3};"
        : "+f"(d[0]), "+f"(d[1]), "+f"(d[2]), "+f"(d[3])
        : "r"(a[0]), "r"(a[1]), "r"(a[2]), "r"(a[3]), "r"(b[0]), "r"(b[1]));
}

// ---------- f32x2 packed helpers (attention) ----------
__device__ __forceinline__ void fma2(ull &acc, ull a, ull b) {
    asm volatile("fma.rn.f32x2 %0, %1, %2, %0;" : "+l"(acc) : "l"(a), "l"(b));
}
__device__ __forceinline__ ull pack2(float lo, float hi) {
    ull r; asm("mov.b64 %0, {%1, %2};" : "=l"(r) : "f"(lo), "f"(hi)); return r;
}
__device__ __forceinline__ ull mul2(ull a, ull b) {
    ull r; asm("mul.rn.f32x2 %0, %1, %2;" : "=l"(r) : "l"(a), "l"(b)); return r;
}
__device__ __forceinline__ float lo2(ull v) { return __uint_as_float((unsigned)v); }
__device__ __forceinline__ float hi2(ull v) { return __uint_as_float((unsigned)(v >> 32)); }

// ============================================================
// Split fp32 -> (hi, lo) bf16
// ============================================================
__global__ void split_bf16(const float4* __restrict__ src, ushort4* __restrict__ hi,
                           ushort4* __restrict__ lo, int n4) {
    int i = blockIdx.x * blockDim.x + threadIdx.x;
    if (i >= n4) return;
    float4 a = src[i];
    __nv_bfloat16 h0 = __float2bfloat16(a.x), h1 = __float2bfloat16(a.y),
                  h2 = __float2bfloat16(a.z), h3 = __float2bfloat16(a.w);
    ushort4 H = make_ushort4(__bfloat16_as_ushort(h0), __bfloat16_as_ushort(h1),
                             __bfloat16_as_ushort(h2), __bfloat16_as_ushort(h3));
    __nv_bfloat16 l0 = __float2bfloat16(a.x - __bfloat162float(h0));
    __nv_bfloat16 l1 = __float2bfloat16(a.y - __bfloat162float(h1));
    __nv_bfloat16 l2 = __float2bfloat16(a.z - __bfloat162float(h2));
    __nv_bfloat16 l3 = __float2bfloat16(a.w - __bfloat162float(h3));
    ushort4 L = make_ushort4(__bfloat16_as_ushort(l0), __bfloat16_as_ushort(l1),
                             __bfloat16_as_ushort(l2), __bfloat16_as_ushort(l3));
    hi[i] = H;
    lo[i] = L;
}

// ============================================================
// Split-bf16 GEMM (NT) on mma.sync: C[M,N] = A[M,K] * B[N,K]^T
// M=8192, N=K=2048. Tile 128x128, 8 warps (64x32 each), BK=32.
// D += Ahi*Bhi + Ahi*Blo + Alo*Bhi  (fp32 accumulators).
// 3-stage cp.async pipeline. Smem rows padded to 80B (conflict-free
// ldmatrix, 16B-aligned cp.async).
// ============================================================
#define GK      2048
#define GBM     128
#define GBN     128
#define GBK     32
#define NCHUNK  (GK / GBK)      // 64
#define ROWB    80              // bytes per smem row (32 bf16 + 8 pad)
#define MATB    (128 * ROWB)    // 10240 bytes per matrix per stage
#define OFF_AHI 0
#define OFF_ALO (1 * MATB)
#define OFF_BHI (2 * MATB)
#define OFF_BLO (3 * MATB)
#define STAGE_B (4 * MATB)      // 40960
#define NSTAGE  3
#define GEMM_SMEM (NSTAGE * STAGE_B)   // 122880

__device__ __forceinline__ void load_stage(
    uint32_t dst,
    const __nv_bfloat16* __restrict__ Ah, const __nv_bfloat16* __restrict__ Al,
    const __nv_bfloat16* __restrict__ Bh, const __nv_bfloat16* __restrict__ Bl,
    int m0, int n0, int kc, int tid)
{
    size_t abase = (size_t)m0 * GK + (size_t)kc * GBK;
    size_t bbase = (size_t)n0 * GK + (size_t)kc * GBK;
    const __nv_bfloat16* srcs[4] = {Ah + abase, Al + abase, Bh + bbase, Bl + bbase};
#pragma unroll
    for (int mat = 0; mat < 4; mat++) {
#pragma unroll
        for (int half = 0; half < 2; half++) {
            int rem = tid + half * 256;        // 0..511
            int row = rem >> 2, seg = rem & 3;
            cpa16(dst + mat * MATB + row * ROWB + seg * 16,
                  (const char*)(srcs[mat] + (size_t)row * GK) + seg * 16);
        }
    }
    CP_COMMIT();
}

__global__ __launch_bounds__(256, 1)
void gemm_mma(const __nv_bfloat16* __restrict__ Ah, const __nv_bfloat16* __restrict__ Al,
              const __nv_bfloat16* __restrict__ Bh, const __nv_bfloat16* __restrict__ Bl,
              float* __restrict__ C) {
    extern __shared__ __align__(1024) uint8_t smem[];
    uint32_t sb = smem_to_u32(smem);
    int tid  = threadIdx.x;
    int wid  = tid >> 5, lane = tid & 31;
    int wm   = wid >> 2, wn = wid & 3;          // 2 x 4 warp grid
    int m0   = blockIdx.y * GBM;
    int n0   = blockIdx.x * GBN;

    float acc[4][4][4];                          // [mfrag][nfrag][reg]
#pragma unroll
    for (int i = 0; i < 4; i++)
#pragma unroll
        for (int j = 0; j < 4; j++)
#pragma unroll
            for (int r = 0; r < 4; r++) acc[i][j][r] = 0.f;

    load_stage(sb + 0 * STAGE_B, Ah, Al, Bh, Bl, m0, n0, 0, tid);
    load_stage(sb + 1 * STAGE_B, Ah, Al, Bh, Bl, m0, n0, 1, tid);

    int lrow = lane & 15;
    int lcol = (lane >> 4) * 16;

    for (int c = 0; c < NCHUNK; c++) {
        if (c >= NCHUNK - 2) { CP_WAIT(0); } else { CP_WAIT(1); }
        __syncthreads();
        if (c + 2 < NCHUNK)
            load_stage(sb + ((c + 2) % NSTAGE) * STAGE_B, Ah, Al, Bh, Bl, m0, n0, c + 2, tid);

        uint32_t base = sb + (c % NSTAGE) * STAGE_B;
#pragma unroll
        for (int ks = 0; ks < 2; ks++) {
            uint32_t kb = ks * 32 + lcol;
            uint32_t ah[4][4], al[4][4];
#pragma unroll
            for (int mf = 0; mf < 4; mf++) {
                uint32_t r = (wm * 64 + mf * 16 + lrow) * ROWB + kb;
                ldsm4(ah[mf][0], ah[mf][1], ah[mf][2], ah[mf][3], base + OFF_AHI + r);
                ldsm4(al[mf][0], al[mf][1], al[mf][2], al[mf][3], base + OFF_ALO + r);
            }
            uint32_t bh[4][2], bl[4][2];
#pragma unroll
            for (int nf2 = 0; nf2 < 2; nf2++) {
                uint32_t r = (wn * 32 + nf2 * 16 + lrow) * ROWB + kb;
                uint32_t t0, t1, t2, t3;
                ldsm4(t0, t1, t2, t3, base + OFF_BHI + r);
                bh[nf2*2][0] = t0; bh[nf2*2][1] = t2;
                bh[nf2*2+1][0] = t1; bh[nf2*2+1][1] = t3;
                ldsm4(t0, t1, t2, t3, base + OFF_BLO + r);
                bl[nf2*2][0] = t0; bl[nf2*2][1] = t2;
                bl[nf2*2+1][0] = t1; bl[nf2*2+1][1] = t3;
            }
#pragma unroll
            for (int mf = 0; mf < 4; mf++)
#pragma unroll
                for (int nf = 0; nf < 4; nf++) {
                    mma16816(acc[mf][nf], ah[mf], bh[nf]);
                    mma16816(acc[mf][nf], ah[mf], bl[nf]);
                    mma16816(acc[mf][nf], al[mf], bh[nf]);
                }
        }
    }

    // Epilogue: d0,d1 -> (row, col..col+1); d2,d3 -> (row+8, col..col+1)
#pragma unroll
    for (int mf = 0; mf < 4; mf++) {
        int row = m0 + wm * 64 + mf * 16 + (lane >> 2);
#pragma unroll
        for (int nf = 0; nf < 4; nf++) {
            int col = n0 + wn * 32 + nf * 8 + (lane & 3) * 2;
            *(float2*)(C + (size_t)row * DD + col) =
                make_float2(acc[mf][nf][0], acc[mf][nf][1]);
            *(float2*)(C + (size_t)(row + 8) * DD + col) =
                make_float2(acc[mf][nf][2], acc[mf][nf][3]);
        }
    }
}

// ============================================================
// RoPE: precompute cos/sin table once (fp64 angles), then apply.
// ============================================================
__global__ void rope_table(float2* __restrict__ tab) {
    int idx = blockIdx.x * blockDim.x + threadIdx.x;   // 65536
    int pos = idx >> 6, j = idx & 63;
    double inv = exp2(-(double)j * 0.20762050593046014);  // 10000^(-j/64)
    float ang = (float)((double)pos * inv);
    float sn, cs;
    sincosf(ang, &sn, &cs);
    tab[idx] = make_float2(cs, sn);
}

__global__ void rope_apply(float* __restrict__ q, float* __restrict__ k,
                           const float2* __restrict__ tab) {
    int idx = blockIdx.x * blockDim.x + threadIdx.x;
    if (idx >= TT * HH * (DHE / 2)) return;
    int j  = idx & 63;
    int th = idx >> 6;
    int h  = th & (HH - 1);
    int t  = th >> 4;
    int pos = t & (SS - 1);
    float2 cs = tab[pos * 64 + j];

    size_t base = (size_t)t * DD + h * DHE + j;
    float q0 = q[base], q1 = q[base + 64];
    q[base]      = q0 * cs.x - q1 * cs.y;
    q[base + 64] = q1 * cs.x + q0 * cs.y;
    float k0 = k[base], k1 = k[base + 64];
    k[base]      = k0 * cs.x - k1 * cs.y;
    k[base + 64] = k1 * cs.x + k0 * cs.y;
}

// ============================================================
// Paged KV scatter: one block per token copies its k,v rows
// ============================================================
__global__ void scatter_kv(const float* __restrict__ k, const float* __restrict__ v,
                           const int* __restrict__ block_table, float* __restrict__ cache) {
    int t   = blockIdx.x;
    int pos = t & (SS - 1);
    int seq = t >> 10;
    int phys = block_table[seq * (SS / PBS) + (pos / PBS)];
    int off  = pos & (PBS - 1);

    for (int i = threadIdx.x; i < 2 * DD / 4; i += blockDim.x) {  // 1024 float4
        int kv  = i >> 9;
        int rem = i & 511;
        int hh  = rem >> 5;
        int d4  = rem & 31;
        const float* src = kv ? v : k;
        float4 val = *(const float4*)(src + (size_t)t * DD + hh * DHE + d4 * 4);
        size_t dst = ((((size_t)phys * 2 + kv) * HH + hh) * PBS + off) * DHE + d4 * 4;
        *(float4*)(cache + dst) = val;
    }
}

// ============================================================
// Flash attention, causal, fp32 with f32x2 packed math.
// ============================================================
#define QTS  64
#define QSTR 132
#define PSTR 65
#define QK_SCALE 0.08838834764831843f   // 1/sqrt(128)

__global__ __launch_bounds__(256)
void attn_kernel(const float* __restrict__ q, const float* __restrict__ kg,
                 const float* __restrict__ vg, float* __restrict__ o) {
    extern __shared__ __align__(16) float sm[];
    float* Qs  = sm;
    float* KVs = Qs + QTS * QSTR;
    float* Ps  = KVs + QTS * QSTR;

    int qt = blockIdx.x, h = blockIdx.y, b = blockIdx.z;
    int tid = threadIdx.x;
    int ty = tid >> 4, tx = tid & 15;
    int r0 = ty * 4, c0 = tx * 4, d0 = tx * 8;
    int qbase = b * SS + qt * QTS;

    for (int i = tid; i < QTS * DHE / 4; i += 256) {
        int r = i >> 5, c4 = i & 31;
        float4 val = *(const float4*)(q + (size_t)(qbase + r) * DD + h * DHE + c4 * 4);
        val.x *= QK_SCALE; val.y *= QK_SCALE; val.z *= QK_SCALE; val.w *= QK_SCALE;
        *(float4*)(Qs + r * QSTR + c4 * 4) = val;
    }

    float m_i[4], l_i[4];
    ull O2[4][4];
#pragma unroll
    for (int i = 0; i < 4; i++) {
        m_i[i] = -INFINITY; l_i[i] = 0.f;
#pragma unroll
        for (int j = 0; j < 4; j++) O2[i][j] = 0ull;
    }

    for (int kt = 0; kt <= qt; kt++) {
        __syncthreads();
        int kbase = b * SS + kt * QTS;
        for (int i = tid; i < QTS * DHE / 4; i += 256) {
            int r = i >> 5, c4 = i & 31;
            *(float4*)(KVs + r * QSTR + c4 * 4) =
                *(const float4*)(kg + (size_t)(kbase + r) * DD + h * DHE + c4 * 4);
        }
        __syncthreads();

        ull acc[4][4];
#pragma unroll
        for (int i = 0; i < 4; i++)
#pragma unroll
            for (int j = 0; j < 4; j++) acc[i][j] = 0ull;

#pragma unroll 4
        for (int d = 0; d < DHE; d += 2) {
            ull a0 = *(const ull*)(Qs + (r0 + 0) * QSTR + d);
            ull a1 = *(const ull*)(Qs + (r0 + 1) * QSTR + d);
            ull a2 = *(const ull*)(Qs + (r0 + 2) * QSTR + d);
            ull a3 = *(const ull*)(Qs + (r0 + 3) * QSTR + d);
            ull b0 = *(const ull*)(KVs + (c0 + 0) * QSTR + d);
            ull b1 = *(const ull*)(KVs + (c0 + 1) * QSTR + d);
            ull b2 = *(const ull*)(KVs + (c0 + 2) * QSTR + d);
            ull b3 = *(const ull*)(KVs + (c0 + 3) * QSTR + d);
            fma2(acc[0][0], a0, b0); fma2(acc[0][1], a0, b1);
            fma2(acc[0][2], a0, b2); fma2(acc[0][3], a0, b3);
            fma2(acc[1][0], a1, b0); fma2(acc[1][1], a1, b1);
            fma2(acc[1][2], a1, b2); fma2(acc[1][3], a1, b3);
            fma2(acc[2][0], a2, b0); fma2(acc[2][1], a2, b1);
            fma2(acc[2][2], a2, b2); fma2(acc[2][3], a2, b3);
            fma2(acc[3][0], a3, b0); fma2(acc[3][1], a3, b1);
            fma2(acc[3][2], a3, b2); fma2(acc[3][3], a3, b3);
        }

        float s[4][4];
#pragma unroll
        for (int i = 0; i < 4; i++)
#pragma unroll
            for (int j = 0; j < 4; j++)
                s[i][j] = lo2(acc[i][j]) + hi2(acc[i][j]);

        if (kt == qt) {
#pragma unroll
            for (int i = 0; i < 4; i++)
#pragma unroll
                for (int j = 0; j < 4; j++)
                    if (c0 + j > r0 + i) s[i][j] = -INFINITY;
        }

#pragma unroll
        for (int i = 0; i < 4; i++) {
            float mx = fmaxf(fmaxf(s[i][0], s[i][1]), fmaxf(s[i][2], s[i][3]));
#pragma unroll
            for (int msk = 8; msk >= 1; msk >>= 1)
                mx = fmaxf(mx, __shfl_xor_sync(0xffffffffu, mx, msk));
            float mn = fmaxf(m_i[i], mx);
            float p0 = __expf(s[i][0] - mn);
            float p1 = __expf(s[i][1] - mn);
            float p2 = __expf(s[i][2] - mn);
            float p3 = __expf(s[i][3] - mn);
            float sum = p0 + p1 + p2 + p3;
#pragma unroll
            for (int msk = 8; msk >= 1; msk >>= 1)
                sum += __shfl_xor_sync(0xffffffffu, sum, msk);
            float al = __expf(m_i[i] - mn);
            l_i[i] = l_i[i] * al + sum;
            m_i[i] = mn;
            ull al2 = pack2(al, al);
#pragma unroll
            for (int j = 0; j < 4; j++) O2[i][j] = mul2(O2[i][j], al2);
            float* pr = Ps + (r0 + i) * PSTR + c0;
            pr[0] = p0; pr[1] = p1; pr[2] = p2; pr[3] = p3;
        }
        __syncthreads();

        for (int i = tid; i < QTS * DHE / 4; i += 256) {
            int r = i >> 5, c4 = i & 31;
            *(float4*)(KVs + r * QSTR + c4 * 4) =
                *(const float4*)(vg + (size_t)(kbase + r) * DD + h * DHE + c4 * 4);
        }
        __syncthreads();

#pragma unroll 2
        for (int c = 0; c < QTS; c++) {
            ull v0 = *(const ull*)(KVs + c * QSTR + d0);
            ull v1 = *(const ull*)(KVs + c * QSTR + d0 + 2);
            ull v2 = *(const ull*)(KVs + c * QSTR + d0 + 4);
            ull v3 = *(const ull*)(KVs + c * QSTR + d0 + 6);
#pragma unroll
            for (int i = 0; i < 4; i++) {
                float p = Ps[(r0 + i) * PSTR + c];
                ull pp = pack2(p, p);
                fma2(O2[i][0], pp, v0);
                fma2(O2[i][1], pp, v1);
                fma2(O2[i][2], pp, v2);
                fma2(O2[i][3], pp, v3);
            }
        }
    }

#pragma unroll
    for (int i = 0; i < 4; i++) {
        float inv = 1.f / l_i[i];
        float4 o0 = make_float4(lo2(O2[i][0]) * inv, hi2(O2[i][0]) * inv,
                                lo2(O2[i][1]) * inv, hi2(O2[i][1]) * inv);
        float4 o1 = make_float4(lo2(O2[i][2]) * inv, hi2(O2[i][2]) * inv,
                                lo2(O2[i][3]) * inv, hi2(O2[i][3]) * inv);
        float* op = o + (size_t)(qbase + r0 + i) * DD + h * DHE + d0;
        *(float4*)(op)     = o0;
        *(float4*)(op + 4) = o1;
    }
}

// ============================================================
// Launch
// ============================================================
extern "C" void kernel_launch(void* const* d_in, const int* in_sizes, int n_in,
                              void* d_out, int out_size) {
    (void)in_sizes; (void)n_in; (void)out_size;
    const float* x      = (const float*)d_in[0];
    const float* Wq     = (const float*)d_in[1];
    const float* Wk     = (const float*)d_in[2];
    const float* Wv     = (const float*)d_in[3];
    const float* Wo     = (const float*)d_in[4];
    const float* kv_in  = (const float*)d_in[5];
    const int*   btab   = (const int*)d_in[7];

    float* out       = (float*)d_out;
    float* cache_out = out + (size_t)TT * DD;

    void* p;
    cudaGetSymbolAddress(&p, g_q);       float* gq = (float*)p;
    cudaGetSymbolAddress(&p, g_k);       float* gk = (float*)p;
    cudaGetSymbolAddress(&p, g_v);       float* gv = (float*)p;
    cudaGetSymbolAddress(&p, g_attn);    float* ga = (float*)p;
    cudaGetSymbolAddress(&p, g_ah);      __nv_bfloat16* ah = (__nv_bfloat16*)p;
    cudaGetSymbolAddress(&p, g_al);      __nv_bfloat16* al = (__nv_bfloat16*)p;
    cudaGetSymbolAddress(&p, g_bh);      __nv_bfloat16* bh = (__nv_bfloat16*)p;
    cudaGetSymbolAddress(&p, g_bl);      __nv_bfloat16* bl = (__nv_bfloat16*)p;
    cudaGetSymbolAddress(&p, g_ropetab); float2* rtab = (float2*)p;

    cudaFuncSetAttribute(gemm_mma, cudaFuncAttributeMaxDynamicSharedMemorySize, GEMM_SMEM);

    // copy input cache (untouched blocks must survive), then scatter overwrites
    cudaMemcpyAsync(cache_out, kv_in,
                    (size_t)NBLK * 2 * HH * PBS * DHE * sizeof(float),
                    cudaMemcpyDeviceToDevice, 0);

    const int nx4 = TT * DD / 4, nw4 = DD * DD / 4;
    dim3 ggrid(DD / GBN, TT / GBM);   // (16, 64)

    // QKV projections on tensor cores (mma.sync, split-bf16)
    split_bf16<<<(nx4 + 255) / 256, 256>>>((const float4*)x, (ushort4*)ah, (ushort4*)al, nx4);
    split_bf16<<<(nw4 + 255) / 256, 256>>>((const float4*)Wq, (ushort4*)bh, (ushort4*)bl, nw4);
    gemm_mma<<<ggrid, 256, GEMM_SMEM>>>(ah, al, bh, bl, gq);
    split_bf16<<<(nw4 + 255) / 256, 256>>>((const float4*)Wk, (ushort4*)bh, (ushort4*)bl, nw4);
    gemm_mma<<<ggrid, 256, GEMM_SMEM>>>(ah, al, bh, bl, gk);
    split_bf16<<<(nw4 + 255) / 256, 256>>>((const float4*)Wv, (ushort4*)bh, (ushort4*)bl, nw4);
    gemm_mma<<<ggrid, 256, GEMM_SMEM>>>(ah, al, bh, bl, gv);

    // RoPE via precomputed table
    rope_table<<<256, 256>>>(rtab);
    int nrope = TT * HH * (DHE / 2);
    rope_apply<<<(nrope + 255) / 256, 256>>>(gq, gk, rtab);

    scatter_kv<<<TT, 256>>>(gk, gv, btab, cache_out);

    size_t smem = (size_t)(QTS * QSTR * 2 + QTS * PSTR) * sizeof(float);
    cudaFuncSetAttribute(attn_kernel, cudaFuncAttributeMaxDynamicSharedMemorySize, (int)smem);
    attn_kernel<<<dim3(SS / QTS, HH, BBQ), 256, smem>>>(gq, gk, gv, ga);

    // Output projection (reuse A-split buffers)
    split_bf16<<<(nx4 + 255) / 256, 256>>>((const float4*)ga, (ushort4*)ah, (ushort4*)al, nx4);
    split_bf16<<<(nw4 + 255) / 256, 256>>>((const float4*)Wo, (ushort4*)bh, (ushort4*)bl, nw4);
    gemm_mma<<<ggrid, 256, GEMM_SMEM>>>(ah, al, bh, bl, out);
}

// round 11
// speedup vs baseline: 2.7598x; 1.4524x over previous
#include <cuda_runtime.h>
#include <cuda_bf16.h>
#include <math.h>
#include <stdint.h>

// Problem constants (fixed by reference setup)
#define TT   8192      // total tokens B*S
#define DD   2048      // d_model
#define HH   16        // heads
#define DHE  128       // head dim
#define BBQ  8         // batch
#define SS   1024      // seq len
#define PBS  256       // page block size
#define NBLK 64        // physical blocks

typedef unsigned long long ull;

// Scratch (static device arrays: allocation-free rule)
__device__ float g_q[(size_t)TT * DD];
__device__ float g_k[(size_t)TT * DD];
__device__ float g_v[(size_t)TT * DD];
__device__ float g_attn[(size_t)TT * DD];
__device__ __nv_bfloat16 g_ah[(size_t)TT * DD];   // A hi split (x, then attn out)
__device__ __nv_bfloat16 g_al[(size_t)TT * DD];   // A lo split
__device__ __nv_bfloat16 g_bh[(size_t)DD * DD];   // W hi split (reused per GEMM)
__device__ __nv_bfloat16 g_bl[(size_t)DD * DD];   // W lo split
__device__ __nv_bfloat16 g_qh[(size_t)TT * DD];   // roped q hi/lo
__device__ __nv_bfloat16 g_ql[(size_t)TT * DD];
__device__ __nv_bfloat16 g_kh[(size_t)TT * DD];   // roped k hi/lo
__device__ __nv_bfloat16 g_kl[(size_t)TT * DD];
__device__ __nv_bfloat16 g_vh[(size_t)TT * DD];   // v hi/lo
__device__ __nv_bfloat16 g_vl[(size_t)TT * DD];
__device__ float2 g_ropetab[SS * 64];             // cos/sin table

// ---------- helpers ----------
__device__ __forceinline__ uint32_t smem_to_u32(const void* smem_ptr) {
    uint32_t addr;
    asm("{ .reg .u64 tmp; cvta.to.shared.u64 tmp, %1; cvt.u32.u64 %0, tmp; }"
        : "=r"(addr) : "l"(smem_ptr));
    return addr;
}
__device__ __forceinline__ void cpa16(uint32_t dst, const void* src) {
    asm volatile("cp.async.cg.shared.global [%0], [%1], 16;" :: "r"(dst), "l"(src));
}
#define CP_COMMIT() asm volatile("cp.async.commit_group;" ::: "memory")
#define CP_WAIT(n)  asm volatile("cp.async.wait_group %0;" :: "n"(n) : "memory")

__device__ __forceinline__ void ldsm4(uint32_t &r0, uint32_t &r1, uint32_t &r2,
                                      uint32_t &r3, uint32_t addr) {
    asm volatile("ldmatrix.sync.aligned.m8n8.x4.shared.b16 {%0,%1,%2,%3}, [%4];"
        : "=r"(r0), "=r"(r1), "=r"(r2), "=r"(r3) : "r"(addr));
}
__device__ __forceinline__ void ldsm4t(uint32_t &r0, uint32_t &r1, uint32_t &r2,
                                       uint32_t &r3, uint32_t addr) {
    asm volatile("ldmatrix.sync.aligned.m8n8.x4.trans.shared.b16 {%0,%1,%2,%3}, [%4];"
        : "=r"(r0), "=r"(r1), "=r"(r2), "=r"(r3) : "r"(addr));
}
__device__ __forceinline__ void mma16816(float* d, const uint32_t* a, const uint32_t* b) {
    asm volatile(
        "mma.sync.aligned.m16n8k16.row.col.f32.bf16.bf16.f32 "
        "{%0,%1,%2,%3}, {%4,%5,%6,%7}, {%8,%9}, {%0,%1,%2,%3};"
        : "+f"(d[0]), "+f"(d[1]), "+f"(d[2]), "+f"(d[3])
        : "r"(a[0]), "r"(a[1]), "r"(a[2]), "r"(a[3]), "r"(b[0]), "r"(b[1]));
}

// ============================================================
// Split fp32 -> (hi, lo) bf16
// ============================================================
__global__ void split_bf16(const float4* __restrict__ src, ushort4* __restrict__ hi,
                           ushort4* __restrict__ lo, int n4) {
    int i = blockIdx.x * blockDim.x + threadIdx.x;
    if (i >= n4) return;
    float4 a = src[i];
    __nv_bfloat16 h0 = __float2bfloat16(a.x), h1 = __float2bfloat16(a.y),
                  h2 = __float2bfloat16(a.z), h3 = __float2bfloat16(a.w);
    ushort4 H = make_ushort4(__bfloat16_as_ushort(h0), __bfloat16_as_ushort(h1),
                             __bfloat16_as_ushort(h2), __bfloat16_as_ushort(h3));
    __nv_bfloat16 l0 = __float2bfloat16(a.x - __bfloat162float(h0));
    __nv_bfloat16 l1 = __float2bfloat16(a.y - __bfloat162float(h1));
    __nv_bfloat16 l2 = __float2bfloat16(a.z - __bfloat162float(h2));
    __nv_bfloat16 l3 = __float2bfloat16(a.w - __bfloat162float(h3));
    ushort4 L = make_ushort4(__bfloat16_as_ushort(l0), __bfloat16_as_ushort(l1),
                             __bfloat16_as_ushort(l2), __bfloat16_as_ushort(l3));
    hi[i] = H;
    lo[i] = L;
}

// ============================================================
// Split-bf16 GEMM (NT) on mma.sync: C[M,N] = A[M,K] * B[N,K]^T
// (unchanged from R10 — at HMMA floor)
// ============================================================
#define GK      2048
#define GBM     128
#define GBN     128
#define GBK     32
#define NCHUNK  (GK / GBK)      // 64
#define ROWB    80              // bytes per smem row (32 bf16 + 8 pad)
#define MATB    (128 * ROWB)    // 10240 bytes per matrix per stage
#define OFF_AHI 0
#define OFF_ALO (1 * MATB)
#define OFF_BHI (2 * MATB)
#define OFF_BLO (3 * MATB)
#define STAGE_B (4 * MATB)      // 40960
#define NSTAGE  3
#define GEMM_SMEM (NSTAGE * STAGE_B)   // 122880

__device__ __forceinline__ void load_stage(
    uint32_t dst,
    const __nv_bfloat16* __restrict__ Ah, const __nv_bfloat16* __restrict__ Al,
    const __nv_bfloat16* __restrict__ Bh, const __nv_bfloat16* __restrict__ Bl,
    int m0, int n0, int kc, int tid)
{
    size_t abase = (size_t)m0 * GK + (size_t)kc * GBK;
    size_t bbase = (size_t)n0 * GK + (size_t)kc * GBK;
    const __nv_bfloat16* srcs[4] = {Ah + abase, Al + abase, Bh + bbase, Bl + bbase};
#pragma unroll
    for (int mat = 0; mat < 4; mat++) {
#pragma unroll
        for (int half = 0; half < 2; half++) {
            int rem = tid + half * 256;        // 0..511
            int row = rem >> 2, seg = rem & 3;
            cpa16(dst + mat * MATB + row * ROWB + seg * 16,
                  (const char*)(srcs[mat] + (size_t)row * GK) + seg * 16);
        }
    }
    CP_COMMIT();
}

__global__ __launch_bounds__(256, 1)
void gemm_mma(const __nv_bfloat16* __restrict__ Ah, const __nv_bfloat16* __restrict__ Al,
              const __nv_bfloat16* __restrict__ Bh, const __nv_bfloat16* __restrict__ Bl,
              float* __restrict__ C) {
    extern __shared__ __align__(1024) uint8_t smem[];
    uint32_t sb = smem_to_u32(smem);
    int tid  = threadIdx.x;
    int wid  = tid >> 5, lane = tid & 31;
    int wm   = wid >> 2, wn = wid & 3;          // 2 x 4 warp grid
    int m0   = blockIdx.y * GBM;
    int n0   = blockIdx.x * GBN;

    float acc[4][4][4];
#pragma unroll
    for (int i = 0; i < 4; i++)
#pragma unroll
        for (int j = 0; j < 4; j++)
#pragma unroll
            for (int r = 0; r < 4; r++) acc[i][j][r] = 0.f;

    load_stage(sb + 0 * STAGE_B, Ah, Al, Bh, Bl, m0, n0, 0, tid);
    load_stage(sb + 1 * STAGE_B, Ah, Al, Bh, Bl, m0, n0, 1, tid);

    int lrow = lane & 15;
    int lcol = (lane >> 4) * 16;

    for (int c = 0; c < NCHUNK; c++) {
        if (c >= NCHUNK - 2) { CP_WAIT(0); } else { CP_WAIT(1); }
        __syncthreads();
        if (c + 2 < NCHUNK)
            load_stage(sb + ((c + 2) % NSTAGE) * STAGE_B, Ah, Al, Bh, Bl, m0, n0, c + 2, tid);

        uint32_t base = sb + (c % NSTAGE) * STAGE_B;
#pragma unroll
        for (int ks = 0; ks < 2; ks++) {
            uint32_t kb = ks * 32 + lcol;
            uint32_t ah[4][4], al[4][4];
#pragma unroll
            for (int mf = 0; mf < 4; mf++) {
                uint32_t r = (wm * 64 + mf * 16 + lrow) * ROWB + kb;
                ldsm4(ah[mf][0], ah[mf][1], ah[mf][2], ah[mf][3], base + OFF_AHI + r);
                ldsm4(al[mf][0], al[mf][1], al[mf][2], al[mf][3], base + OFF_ALO + r);
            }
            uint32_t bh[4][2], bl[4][2];
#pragma unroll
            for (int nf2 = 0; nf2 < 2; nf2++) {
                uint32_t r = (wn * 32 + nf2 * 16 + lrow) * ROWB + kb;
                uint32_t t0, t1, t2, t3;
                ldsm4(t0, t1, t2, t3, base + OFF_BHI + r);
                bh[nf2*2][0] = t0; bh[nf2*2][1] = t2;
                bh[nf2*2+1][0] = t1; bh[nf2*2+1][1] = t3;
                ldsm4(t0, t1, t2, t3, base + OFF_BLO + r);
                bl[nf2*2][0] = t0; bl[nf2*2][1] = t2;
                bl[nf2*2+1][0] = t1; bl[nf2*2+1][1] = t3;
            }
#pragma unroll
            for (int mf = 0; mf < 4; mf++)
#pragma unroll
                for (int nf = 0; nf < 4; nf++) {
                    mma16816(acc[mf][nf], ah[mf], bh[nf]);
                    mma16816(acc[mf][nf], ah[mf], bl[nf]);
                    mma16816(acc[mf][nf], al[mf], bh[nf]);
                }
        }
    }

#pragma unroll
    for (int mf = 0; mf < 4; mf++) {
        int row = m0 + wm * 64 + mf * 16 + (lane >> 2);
#pragma unroll
        for (int nf = 0; nf < 4; nf++) {
            int col = n0 + wn * 32 + nf * 8 + (lane & 3) * 2;
            *(float2*)(C + (size_t)row * DD + col) =
                make_float2(acc[mf][nf][0], acc[mf][nf][1]);
            *(float2*)(C + (size_t)(row + 8) * DD + col) =
                make_float2(acc[mf][nf][2], acc[mf][nf][3]);
        }
    }
}

// ============================================================
// RoPE cos/sin table (fp64 angles)
// ============================================================
__global__ void rope_table(float2* __restrict__ tab) {
    int idx = blockIdx.x * blockDim.x + threadIdx.x;   // 65536
    int pos = idx >> 6, j = idx & 63;
    double inv = exp2(-(double)j * 0.20762050593046014);  // 10000^(-j/64)
    float ang = (float)((double)pos * inv);
    float sn, cs;
    sincosf(ang, &sn, &cs);
    tab[idx] = make_float2(cs, sn);
}

// ============================================================
// Fused rope + bf16 hi/lo split + paged KV scatter.
// One block per token.
// ============================================================
__device__ __forceinline__ void store_split(__nv_bfloat16* H, __nv_bfloat16* L,
                                            size_t idx, float v) {
    __nv_bfloat16 h = __float2bfloat16(v);
    H[idx] = h;
    L[idx] = __float2bfloat16(v - __bfloat162float(h));
}

__global__ void rope_split_scatter(
    const float* __restrict__ gq, const float* __restrict__ gk,
    const float* __restrict__ gv, const int* __restrict__ btab,
    const float2* __restrict__ rtab,
    __nv_bfloat16* __restrict__ qh, __nv_bfloat16* __restrict__ ql,
    __nv_bfloat16* __restrict__ kh, __nv_bfloat16* __restrict__ kl,
    __nv_bfloat16* __restrict__ vh, __nv_bfloat16* __restrict__ vl,
    float* __restrict__ cache)
{
    int t   = blockIdx.x;
    int tid = threadIdx.x;
    int pos = t & (SS - 1);
    int seq = t >> 10;
    int phys = btab[seq * (SS / PBS) + (pos >> 8)];
    int off  = pos & (PBS - 1);

    for (int i = tid; i < 1024; i += 256) {      // (h, j) pairs, j < 64
        int hh = i >> 6, j = i & 63;
        float2 cs = rtab[pos * 64 + j];
        size_t base = (size_t)t * DD + hh * DHE + j;
        float q0 = gq[base], q1 = gq[base + 64];
        float qr0 = q0 * cs.x - q1 * cs.y;
        float qr1 = q1 * cs.x + q0 * cs.y;
        store_split(qh, ql, base,      qr0);
        store_split(qh, ql, base + 64, qr1);
        float k0 = gk[base], k1 = gk[base + 64];
        float kr0 = k0 * cs.x - k1 * cs.y;
        float kr1 = k1 * cs.x + k0 * cs.y;
        store_split(kh, kl, base,      kr0);
        store_split(kh, kl, base + 64, kr1);
        size_t cdst = ((((size_t)phys * 2 + 0) * HH + hh) * PBS + off) * DHE + j;
        cache[cdst]      = kr0;
        cache[cdst + 64] = kr1;
    }
    for (int i = tid; i < 2048; i += 256) {
        int hh = i >> 7, d = i & 127;
        float v = gv[(size_t)t * DD + i];
        store_split(vh, vl, (size_t)t * DD + i, v);
        cache[((((size_t)phys * 2 + 1) * HH + hh) * PBS + off) * DHE + d] = v;
    }
}

// ============================================================
// Flash attention on mma.sync, split-bf16 (3-term) for QK and PV.
// CTA: 128 q rows x 1 head x 1 batch; 8 warps, 16 q-rows each.
// K/V tiles of 64, double-buffered cp.async.
// ============================================================
#define AQT   128
#define AKT   64
#define AROWB 272                 // 128 bf16 (256B) + 16B pad
#define SM_QHI 0
#define SM_QLO (128 * AROWB)      // 34816
#define SM_KV0 (2 * 128 * AROWB)  // 69632
#define MATKV  (64 * AROWB)       // 17408: Khi | Klo | Vhi | Vlo
#define KVSTG  (4 * MATKV)        // 69632
#define ASMEM  (SM_KV0 + 2 * KVSTG)  // 208896
#define QK_SCALE 0.08838834764831843f   // 1/sqrt(128)

__device__ __forceinline__ uint32_t packsplit(float a, float b, uint32_t &lo) {
    __nv_bfloat16 ha = __float2bfloat16(a), hb = __float2bfloat16(b);
    __nv_bfloat162 l2 = __floats2bfloat162_rn(a - __bfloat162float(ha),
                                              b - __bfloat162float(hb));
    lo = *(uint32_t*)&l2;
    __nv_bfloat162 h2;
    h2.x = ha; h2.y = hb;
    return *(uint32_t*)&h2;
}

__device__ __forceinline__ void attn_load_kv(
    uint32_t st, const __nv_bfloat16* kh, const __nv_bfloat16* kl,
    const __nv_bfloat16* vh, const __nv_bfloat16* vl,
    int kbase, size_t hoff, int tid)
{
    for (int i = tid; i < 1024; i += 256) {      // 64 rows x 16 segs
        int r = i >> 4, seg = (i & 15) * 16;
        size_t grow = (size_t)(kbase + r) * DD + hoff;
        uint32_t d = st + r * AROWB + seg;
        cpa16(d,             (const char*)(kh + grow) + seg);
        cpa16(d + MATKV,     (const char*)(kl + grow) + seg);
        cpa16(d + 2 * MATKV, (const char*)(vh + grow) + seg);
        cpa16(d + 3 * MATKV, (const char*)(vl + grow) + seg);
    }
    CP_COMMIT();
}

__global__ __launch_bounds__(256, 1)
void attn_mma(const __nv_bfloat16* __restrict__ qh, const __nv_bfloat16* __restrict__ ql,
              const __nv_bfloat16* __restrict__ kh, const __nv_bfloat16* __restrict__ kl,
              const __nv_bfloat16* __restrict__ vh, const __nv_bfloat16* __restrict__ vl,
              float* __restrict__ o) {
    extern __shared__ __align__(1024) uint8_t smem[];
    uint32_t sb = smem_to_u32(smem);
    int tid  = threadIdx.x;
    int wid  = tid >> 5, lane = tid & 31;
    int g    = lane >> 2, tq = lane & 3;
    int qt   = (gridDim.x - 1) - blockIdx.x;      // big tiles first
    int h    = blockIdx.y, b = blockIdx.z;
    int qbase = b * SS + qt * AQT;
    size_t hoff = (size_t)h * DHE;

    // load Q hi/lo tile (128 rows x 256B each)
    for (int i = tid; i < 2048; i += 256) {
        int r = i >> 4, seg = (i & 15) * 16;
        size_t grow = (size_t)(qbase + r) * DD + hoff;
        cpa16(sb + SM_QHI + r * AROWB + seg, (const char*)(qh + grow) + seg);
        cpa16(sb + SM_QLO + r * AROWB + seg, (const char*)(ql + grow) + seg);
    }
    // prefetch kt=0 (same commit group as Q)
    attn_load_kv(sb + SM_KV0, kh, kl, vh, vl, b * SS, hoff, tid);

    float Oa[16][4];
#pragma unroll
    for (int i = 0; i < 16; i++)
#pragma unroll
        for (int j = 0; j < 4; j++) Oa[i][j] = 0.f;
    float m0v = -1e30f, m1v = -1e30f, l0 = 0.f, l1 = 0.f;
    int row0 = qt * AQT + wid * 16 + g;          // seq-local q position
    int ktmax = 2 * qt + 1;
    int lrow = lane & 15, lc16 = (lane >> 4) * 16;

    for (int kt = 0; kt <= ktmax; kt++) {
        int s = kt & 1;
        __syncthreads();                         // stage s^1 free for reuse
        if (kt < ktmax) {
            attn_load_kv(sb + SM_KV0 + (s ^ 1) * KVSTG, kh, kl, vh, vl,
                         b * SS + (kt + 1) * AKT, hoff, tid);
            CP_WAIT(1);
        } else {
            CP_WAIT(0);
        }
        __syncthreads();

        uint32_t kvs = sb + SM_KV0 + s * KVSTG;

        // ---- scores S = Q K^T (3-term split) ----
        float sacc[8][4];
#pragma unroll
        for (int i = 0; i < 8; i++)
#pragma unroll
            for (int j = 0; j < 4; j++) sacc[i][j] = 0.f;

#pragma unroll
        for (int kc = 0; kc < 8; kc++) {
            uint32_t qa = sb + SM_QHI + (uint32_t)((wid * 16 + lrow) * AROWB + kc * 32 + lc16);
            uint32_t qhif[4], qlof[4];
            ldsm4(qhif[0], qhif[1], qhif[2], qhif[3], qa);
            ldsm4(qlof[0], qlof[1], qlof[2], qlof[3], qa + (SM_QLO - SM_QHI));
#pragma unroll
            for (int nf2 = 0; nf2 < 4; nf2++) {
                uint32_t ka = kvs + (uint32_t)((nf2 * 16 + lrow) * AROWB + kc * 32 + lc16);
                uint32_t t0, t1, t2, t3, u0, u1, u2, u3;
                ldsm4(t0, t1, t2, t3, ka);              // K hi
                ldsm4(u0, u1, u2, u3, ka + MATKV);      // K lo
                uint32_t bh0[2] = {t0, t2}, bh1[2] = {t1, t3};
                uint32_t bl0[2] = {u0, u2}, bl1[2] = {u1, u3};
                mma16816(sacc[2*nf2],   qhif, bh0);
                mma16816(sacc[2*nf2],   qlof, bh0);
                mma16816(sacc[2*nf2],   qhif, bl0);
                mma16816(sacc[2*nf2+1], qhif, bh1);
                mma16816(sacc[2*nf2+1], qlof, bh1);
                mma16816(sacc[2*nf2+1], qhif, bl1);
            }
        }

        // ---- causal mask (only diagonal tiles) ----
        if (kt >= 2 * qt) {
            int colb = kt * AKT + tq * 2;
#pragma unroll
            for (int nf = 0; nf < 8; nf++) {
                int c0 = colb + nf * 8, c1 = c0 + 1;
                if (c0 > row0)     sacc[nf][0] = -1e30f;
                if (c1 > row0)     sacc[nf][1] = -1e30f;
                if (c0 > row0 + 8) sacc[nf][2] = -1e30f;
                if (c1 > row0 + 8) sacc[nf][3] = -1e30f;
            }
        }

        // ---- online softmax ----
        float mx0 = -1e30f, mx1 = -1e30f;
#pragma unroll
        for (int nf = 0; nf < 8; nf++) {
            mx0 = fmaxf(mx0, fmaxf(sacc[nf][0], sacc[nf][1]));
            mx1 = fmaxf(mx1, fmaxf(sacc[nf][2], sacc[nf][3]));
        }
        mx0 = fmaxf(mx0, __shfl_xor_sync(0xffffffffu, mx0, 1));
        mx0 = fmaxf(mx0, __shfl_xor_sync(0xffffffffu, mx0, 2));
        mx1 = fmaxf(mx1, __shfl_xor_sync(0xffffffffu, mx1, 1));
        mx1 = fmaxf(mx1, __shfl_xor_sync(0xffffffffu, mx1, 2));
        float mn0 = fmaxf(m0v, mx0), mn1 = fmaxf(m1v, mx1);
        float al0 = __expf(QK_SCALE * (m0v - mn0));
        float al1 = __expf(QK_SCALE * (m1v - mn1));
        m0v = mn0; m1v = mn1;

        float sum0 = 0.f, sum1 = 0.f;
        uint32_t phi[4][4], plo[4][4];
#pragma unroll
        for (int kc = 0; kc < 4; kc++) {
            float p00 = __expf(QK_SCALE * (sacc[2*kc][0]   - mn0));
            float p01 = __expf(QK_SCALE * (sacc[2*kc][1]   - mn0));
            float p02 = __expf(QK_SCALE * (sacc[2*kc][2]   - mn1));
            float p03 = __expf(QK_SCALE * (sacc[2*kc][3]   - mn1));
            float p10 = __expf(QK_SCALE * (sacc[2*kc+1][0] - mn0));
            float p11 = __expf(QK_SCALE * (sacc[2*kc+1][1] - mn0));
            float p12 = __expf(QK_SCALE * (sacc[2*kc+1][2] - mn1));
            float p13 = __expf(QK_SCALE * (sacc[2*kc+1][3] - mn1));
            sum0 += (p00 + p01) + (p10 + p11);
            sum1 += (p02 + p03) + (p12 + p13);
            phi[kc][0] = packsplit(p00, p01, plo[kc][0]);
            phi[kc][1] = packsplit(p02, p03, plo[kc][1]);
            phi[kc][2] = packsplit(p10, p11, plo[kc][2]);
            phi[kc][3] = packsplit(p12, p13, plo[kc][3]);
        }
        sum0 += __shfl_xor_sync(0xffffffffu, sum0, 1);
        sum0 += __shfl_xor_sync(0xffffffffu, sum0, 2);
        sum1 += __shfl_xor_sync(0xffffffffu, sum1, 1);
        sum1 += __shfl_xor_sync(0xffffffffu, sum1, 2);
        l0 = l0 * al0 + sum0;
        l1 = l1 * al1 + sum1;
#pragma unroll
        for (int nf = 0; nf < 16; nf++) {
            Oa[nf][0] *= al0; Oa[nf][1] *= al0;
            Oa[nf][2] *= al1; Oa[nf][3] *= al1;
        }

        // ---- O += P V (3-term split; V frags via ldmatrix.trans) ----
#pragma unroll
        for (int kc = 0; kc < 4; kc++) {
#pragma unroll
            for (int nf2 = 0; nf2 < 8; nf2++) {
                uint32_t va = kvs + 2 * MATKV +
                              (uint32_t)((kc * 16 + lrow) * AROWB + nf2 * 32 + lc16);
                uint32_t t0, t1, t2, t3, u0, u1, u2, u3;
                ldsm4t(t0, t1, t2, t3, va);             // V hi
                ldsm4t(u0, u1, u2, u3, va + MATKV);     // V lo
                uint32_t bh0[2] = {t0, t1}, bh1[2] = {t2, t3};
                uint32_t bl0[2] = {u0, u1}, bl1[2] = {u2, u3};
                mma16816(Oa[2*nf2],   phi[kc], bh0);
                mma16816(Oa[2*nf2],   plo[kc], bh0);
                mma16816(Oa[2*nf2],   phi[kc], bl0);
                mma16816(Oa[2*nf2+1], phi[kc], bh1);
                mma16816(Oa[2*nf2+1], plo[kc], bh1);
                mma16816(Oa[2*nf2+1], phi[kc], bl1);
            }
        }
    }

    // ---- epilogue ----
    float il0 = 1.f / l0, il1 = 1.f / l1;
    float* op0 = o + (size_t)(qbase + wid * 16 + g) * DD + hoff;
    float* op1 = op0 + 8 * DD;
#pragma unroll
    for (int nf = 0; nf < 16; nf++) {
        int c = nf * 8 + tq * 2;
        *(float2*)(op0 + c) = make_float2(Oa[nf][0] * il0, Oa[nf][1] * il0);
        *(float2*)(op1 + c) = make_float2(Oa[nf][2] * il1, Oa[nf][3] * il1);
    }
}

// ============================================================
// Launch
// ============================================================
extern "C" void kernel_launch(void* const* d_in, const int* in_sizes, int n_in,
                              void* d_out, int out_size) {
    (void)in_sizes; (void)n_in; (void)out_size;
    const float* x      = (const float*)d_in[0];
    const float* Wq     = (const float*)d_in[1];
    const float* Wk     = (const float*)d_in[2];
    const float* Wv     = (const float*)d_in[3];
    const float* Wo     = (const float*)d_in[4];
    const float* kv_in  = (const float*)d_in[5];
    const int*   btab   = (const int*)d_in[7];

    float* out       = (float*)d_out;
    float* cache_out = out + (size_t)TT * DD;

    void* p;
    cudaGetSymbolAddress(&p, g_q);       float* gq = (float*)p;
    cudaGetSymbolAddress(&p, g_k);       float* gk = (float*)p;
    cudaGetSymbolAddress(&p, g_v);       float* gv = (float*)p;
    cudaGetSymbolAddress(&p, g_attn);    float* ga = (float*)p;
    cudaGetSymbolAddress(&p, g_ah);      __nv_bfloat16* ah = (__nv_bfloat16*)p;
    cudaGetSymbolAddress(&p, g_al);      __nv_bfloat16* al = (__nv_bfloat16*)p;
    cudaGetSymbolAddress(&p, g_bh);      __nv_bfloat16* bh = (__nv_bfloat16*)p;
    cudaGetSymbolAddress(&p, g_bl);      __nv_bfloat16* bl = (__nv_bfloat16*)p;
    cudaGetSymbolAddress(&p, g_qh);      __nv_bfloat16* qh = (__nv_bfloat16*)p;
    cudaGetSymbolAddress(&p, g_ql);      __nv_bfloat16* ql = (__nv_bfloat16*)p;
    cudaGetSymbolAddress(&p, g_kh);      __nv_bfloat16* kh = (__nv_bfloat16*)p;
    cudaGetSymbolAddress(&p, g_kl);      __nv_bfloat16* kl = (__nv_bfloat16*)p;
    cudaGetSymbolAddress(&p, g_vh);      __nv_bfloat16* vh = (__nv_bfloat16*)p;
    cudaGetSymbolAddress(&p, g_vl);      __nv_bfloat16* vl = (__nv_bfloat16*)p;
    cudaGetSymbolAddress(&p, g_ropetab); float2* rtab = (float2*)p;

    cudaFuncSetAttribute(gemm_mma, cudaFuncAttributeMaxDynamicSharedMemorySize, GEMM_SMEM);
    cudaFuncSetAttribute(attn_mma, cudaFuncAttributeMaxDynamicSharedMemorySize, ASMEM);

    // copy input cache (untouched blocks must survive), then scatter overwrites
    cudaMemcpyAsync(cache_out, kv_in,
                    (size_t)NBLK * 2 * HH * PBS * DHE * sizeof(float),
                    cudaMemcpyDeviceToDevice, 0);

    const int nx4 = TT * DD / 4, nw4 = DD * DD / 4;
    dim3 ggrid(DD / GBN, TT / GBM);   // (16, 64)

    // QKV projections (mma.sync, split-bf16)
    split_bf16<<<(nx4 + 255) / 256, 256>>>((const float4*)x, (ushort4*)ah, (ushort4*)al, nx4);
    split_bf16<<<(nw4 + 255) / 256, 256>>>((const float4*)Wq, (ushort4*)bh, (ushort4*)bl, nw4);
    gemm_mma<<<ggrid, 256, GEMM_SMEM>>>(ah, al, bh, bl, gq);
    split_bf16<<<(nw4 + 255) / 256, 256>>>((const float4*)Wk, (ushort4*)bh, (ushort4*)bl, nw4);
    gemm_mma<<<ggrid, 256, GEMM_SMEM>>>(ah, al, bh, bl, gk);
    split_bf16<<<(nw4 + 255) / 256, 256>>>((const float4*)Wv, (ushort4*)bh, (ushort4*)bl, nw4);
    gemm_mma<<<ggrid, 256, GEMM_SMEM>>>(ah, al, bh, bl, gv);

    // fused RoPE + split + paged KV scatter
    rope_table<<<256, 256>>>(rtab);
    rope_split_scatter<<<TT, 256>>>(gq, gk, gv, btab, rtab,
                                    qh, ql, kh, kl, vh, vl, cache_out);

    // Wo split early (independent of attention)
    split_bf16<<<(nw4 + 255) / 256, 256>>>((const float4*)Wo, (ushort4*)bh, (ushort4*)bl, nw4);

    // attention (mma.sync flash, split-bf16)
    attn_mma<<<dim3(SS / AQT, HH, BBQ), 256, ASMEM>>>(qh, ql, kh, kl, vh, vl, ga);

    // output projection
    split_bf16<<<(nx4 + 255) / 256, 256>>>((const float4*)ga, (ushort4*)ah, (ushort4*)al, nx4);
    gemm_mma<<<ggrid, 256, GEMM_SMEM>>>(ah, al, bh, bl, out);
}

// round 12
// speedup vs baseline: 4.2250x; 1.5309x over previous
#include <cuda_runtime.h>
#include <cuda_fp16.h>
#include <math.h>
#include <stdint.h>

// Problem constants (fixed by reference setup)
#define TT   8192      // total tokens B*S
#define DD   2048      // d_model
#define HH   16        // heads
#define DHE  128       // head dim
#define BBQ  8         // batch
#define SS   1024      // seq len
#define PBS  256       // page block size
#define NBLK 64        // physical blocks

// Scratch (static device arrays: allocation-free rule)
__device__ float  g_qkv[(size_t)TT * 3 * DD];      // fused QKV projection output
__device__ __half g_ah[(size_t)TT * DD];           // A hi split (x, then attn out)
__device__ __half g_al[(size_t)TT * DD];           // A lo split
__device__ __half g_wh[(size_t)3 * DD * DD];       // weights fp16 (Wq|Wk|Wv, then Wo)
__device__ __half g_qh[(size_t)TT * DD];           // roped q hi/lo
__device__ __half g_ql[(size_t)TT * DD];
__device__ __half g_kh[(size_t)TT * DD];           // roped k hi/lo
__device__ __half g_kl[(size_t)TT * DD];
__device__ __half g_vh[(size_t)TT * DD];           // v fp16 (single)
__device__ float2 g_ropetab[SS * 64];              // cos/sin table

// ---------- helpers ----------
__device__ __forceinline__ uint32_t smem_to_u32(const void* smem_ptr) {
    uint32_t addr;
    asm("{ .reg .u64 tmp; cvta.to.shared.u64 tmp, %1; cvt.u32.u64 %0, tmp; }"
        : "=r"(addr) : "l"(smem_ptr));
    return addr;
}
__device__ __forceinline__ void cpa16(uint32_t dst, const void* src) {
    asm volatile("cp.async.cg.shared.global [%0], [%1], 16;" :: "r"(dst), "l"(src));
}
#define CP_COMMIT() asm volatile("cp.async.commit_group;" ::: "memory")
#define CP_WAIT(n)  asm volatile("cp.async.wait_group %0;" :: "n"(n) : "memory")

__device__ __forceinline__ void ldsm4(uint32_t &r0, uint32_t &r1, uint32_t &r2,
                                      uint32_t &r3, uint32_t addr) {
    asm volatile("ldmatrix.sync.aligned.m8n8.x4.shared.b16 {%0,%1,%2,%3}, [%4];"
        : "=r"(r0), "=r"(r1), "=r"(r2), "=r"(r3) : "r"(addr));
}
__device__ __forceinline__ void ldsm4t(uint32_t &r0, uint32_t &r1, uint32_t &r2,
                                       uint32_t &r3, uint32_t addr) {
    asm volatile("ldmatrix.sync.aligned.m8n8.x4.trans.shared.b16 {%0,%1,%2,%3}, [%4];"
        : "=r"(r0), "=r"(r1), "=r"(r2), "=r"(r3) : "r"(addr));
}
__device__ __forceinline__ void mma16816(float* d, const uint32_t* a, const uint32_t* b) {
    asm volatile(
        "mma.sync.aligned.m16n8k16.row.col.f32.f16.f16.f32 "
        "{%0,%1,%2,%3}, {%4,%5,%6,%7}, {%8,%9}, {%0,%1,%2,%3};"
        : "+f"(d[0]), "+f"(d[1]), "+f"(d[2]), "+f"(d[3])
        : "r"(a[0]), "r"(a[1]), "r"(a[2]), "r"(a[3]), "r"(b[0]), "r"(b[1]));
}

// ============================================================
// fp32 -> fp16 conversions
// ============================================================
__global__ void split_half(const float4* __restrict__ src, ushort4* __restrict__ hi,
                           ushort4* __restrict__ lo, int n4) {
    int i = blockIdx.x * blockDim.x + threadIdx.x;
    if (i >= n4) return;
    float4 a = src[i];
    __half h0 = __float2half_rn(a.x), h1 = __float2half_rn(a.y),
           h2 = __float2half_rn(a.z), h3 = __float2half_rn(a.w);
    hi[i] = make_ushort4(__half_as_ushort(h0), __half_as_ushort(h1),
                         __half_as_ushort(h2), __half_as_ushort(h3));
    lo[i] = make_ushort4(
        __half_as_ushort(__float2half_rn(a.x - __half2float(h0))),
        __half_as_ushort(__float2half_rn(a.y - __half2float(h1))),
        __half_as_ushort(__float2half_rn(a.z - __half2float(h2))),
        __half_as_ushort(__float2half_rn(a.w - __half2float(h3))));
}

__global__ void to_half(const float4* __restrict__ src, ushort4* __restrict__ dst, int n4) {
    int i = blockIdx.x * blockDim.x + threadIdx.x;
    if (i >= n4) return;
    float4 a = src[i];
    dst[i] = make_ushort4(__half_as_ushort(__float2half_rn(a.x)),
                          __half_as_ushort(__float2half_rn(a.y)),
                          __half_as_ushort(__float2half_rn(a.z)),
                          __half_as_ushort(__float2half_rn(a.w)));
}

// ============================================================
// 2-term split-fp16 GEMM (NT) on mma.sync:
// C[M,N] = A[M,K] * W[N,K]^T,  D += Ahi*W + Alo*W  (fp32 acc).
// Tile 128x128, 8 warps (64x32 each), BK=32, 3-stage cp.async.
// Output row stride is a parameter (supports fused-QKV N=6144).
// ============================================================
#define GK      2048
#define GBM     128
#define GBN     128
#define GBK     32
#define NCHUNK  (GK / GBK)      // 64
#define ROWB    80              // bytes per smem row (32 fp16 + 8 pad)
#define MATB    (128 * ROWB)    // 10240 bytes per matrix per stage
#define OFF_AHI 0
#define OFF_ALO (1 * MATB)
#define OFF_B   (2 * MATB)
#define STAGE_B (3 * MATB)      // 30720
#define NSTAGE  3
#define GEMM_SMEM (NSTAGE * STAGE_B)   // 92160

__device__ __forceinline__ void load_stage(
    uint32_t dst,
    const __half* __restrict__ Ah, const __half* __restrict__ Al,
    const __half* __restrict__ W,
    int m0, int n0, int kc, int tid)
{
    size_t abase = (size_t)m0 * GK + (size_t)kc * GBK;
    size_t bbase = (size_t)n0 * GK + (size_t)kc * GBK;
    const __half* srcs[3] = {Ah + abase, Al + abase, W + bbase};
#pragma unroll
    for (int mat = 0; mat < 3; mat++) {
#pragma unroll
        for (int half_i = 0; half_i < 2; half_i++) {
            int rem = tid + half_i * 256;      // 0..511
            int row = rem >> 2, seg = rem & 3;
            cpa16(dst + mat * MATB + row * ROWB + seg * 16,
                  (const char*)(srcs[mat] + (size_t)row * GK) + seg * 16);
        }
    }
    CP_COMMIT();
}

__global__ __launch_bounds__(256, 1)
void gemm_mma(const __half* __restrict__ Ah, const __half* __restrict__ Al,
              const __half* __restrict__ W, float* __restrict__ C, int nstride) {
    extern __shared__ __align__(1024) uint8_t smem[];
    uint32_t sb = smem_to_u32(smem);
    int tid  = threadIdx.x;
    int wid  = tid >> 5, lane = tid & 31;
    int wm   = wid >> 2, wn = wid & 3;          // 2 x 4 warp grid
    int m0   = blockIdx.y * GBM;
    int n0   = blockIdx.x * GBN;

    float acc[4][4][4];
#pragma unroll
    for (int i = 0; i < 4; i++)
#pragma unroll
        for (int j = 0; j < 4; j++)
#pragma unroll
            for (int r = 0; r < 4; r++) acc[i][j][r] = 0.f;

    load_stage(sb + 0 * STAGE_B, Ah, Al, W, m0, n0, 0, tid);
    load_stage(sb + 1 * STAGE_B, Ah, Al, W, m0, n0, 1, tid);

    int lrow = lane & 15;
    int lcol = (lane >> 4) * 16;

    for (int c = 0; c < NCHUNK; c++) {
        if (c >= NCHUNK - 2) { CP_WAIT(0); } else { CP_WAIT(1); }
        __syncthreads();
        if (c + 2 < NCHUNK)
            load_stage(sb + ((c + 2) % NSTAGE) * STAGE_B, Ah, Al, W, m0, n0, c + 2, tid);

        uint32_t base = sb + (c % NSTAGE) * STAGE_B;
#pragma unroll
        for (int ks = 0; ks < 2; ks++) {
            uint32_t kb = ks * 32 + lcol;
            uint32_t ah[4][4], al[4][4];
#pragma unroll
            for (int mf = 0; mf < 4; mf++) {
                uint32_t r = (wm * 64 + mf * 16 + lrow) * ROWB + kb;
                ldsm4(ah[mf][0], ah[mf][1], ah[mf][2], ah[mf][3], base + OFF_AHI + r);
                ldsm4(al[mf][0], al[mf][1], al[mf][2], al[mf][3], base + OFF_ALO + r);
            }
            uint32_t bf[4][2];
#pragma unroll
            for (int nf2 = 0; nf2 < 2; nf2++) {
                uint32_t r = (wn * 32 + nf2 * 16 + lrow) * ROWB + kb;
                uint32_t t0, t1, t2, t3;
                ldsm4(t0, t1, t2, t3, base + OFF_B + r);
                bf[nf2*2][0] = t0; bf[nf2*2][1] = t2;
                bf[nf2*2+1][0] = t1; bf[nf2*2+1][1] = t3;
            }
#pragma unroll
            for (int mf = 0; mf < 4; mf++)
#pragma unroll
                for (int nf = 0; nf < 4; nf++) {
                    mma16816(acc[mf][nf], ah[mf], bf[nf]);
                    mma16816(acc[mf][nf], al[mf], bf[nf]);
                }
        }
    }

#pragma unroll
    for (int mf = 0; mf < 4; mf++) {
        int row = m0 + wm * 64 + mf * 16 + (lane >> 2);
#pragma unroll
        for (int nf = 0; nf < 4; nf++) {
            int col = n0 + wn * 32 + nf * 8 + (lane & 3) * 2;
            *(float2*)(C + (size_t)row * nstride + col) =
                make_float2(acc[mf][nf][0], acc[mf][nf][1]);
            *(float2*)(C + (size_t)(row + 8) * nstride + col) =
                make_float2(acc[mf][nf][2], acc[mf][nf][3]);
        }
    }
}

// ============================================================
// RoPE cos/sin table (fp64 angles)
// ============================================================
__global__ void rope_table(float2* __restrict__ tab) {
    int idx = blockIdx.x * blockDim.x + threadIdx.x;   // 65536
    int pos = idx >> 6, j = idx & 63;
    double inv = exp2(-(double)j * 0.20762050593046014);  // 10000^(-j/64)
    float ang = (float)((double)pos * inv);
    float sn, cs;
    sincosf(ang, &sn, &cs);
    tab[idx] = make_float2(cs, sn);
}

// ============================================================
// Fused rope + fp16 hi/lo split + paged KV scatter.
// Reads fused qkv buffer [T, 6144]. One block per token.
// ============================================================
__device__ __forceinline__ void store_split(__half* H, __half* L, size_t idx, float v) {
    __half h = __float2half_rn(v);
    H[idx] = h;
    L[idx] = __float2half_rn(v - __half2float(h));
}

__global__ void rope_split_scatter(
    const float* __restrict__ qkv, const int* __restrict__ btab,
    const float2* __restrict__ rtab,
    __half* __restrict__ qh, __half* __restrict__ ql,
    __half* __restrict__ kh, __half* __restrict__ kl,
    __half* __restrict__ vh, float* __restrict__ cache)
{
    int t   = blockIdx.x;
    int tid = threadIdx.x;
    int pos = t & (SS - 1);
    int seq = t >> 10;
    int phys = btab[seq * (SS / PBS) + (pos >> 8)];
    int off  = pos & (PBS - 1);
    const float* row = qkv + (size_t)t * (3 * DD);

    for (int i = tid; i < 1024; i += 256) {      // (h, j) pairs, j < 64
        int hh = i >> 6, j = i & 63;
        float2 cs = rtab[pos * 64 + j];
        size_t base = (size_t)t * DD + hh * DHE + j;
        float q0 = row[hh * DHE + j], q1 = row[hh * DHE + j + 64];
        store_split(qh, ql, base,      q0 * cs.x - q1 * cs.y);
        store_split(qh, ql, base + 64, q1 * cs.x + q0 * cs.y);
        float k0 = row[DD + hh * DHE + j], k1 = row[DD + hh * DHE + j + 64];
        float kr0 = k0 * cs.x - k1 * cs.y;
        float kr1 = k1 * cs.x + k0 * cs.y;
        store_split(kh, kl, base,      kr0);
        store_split(kh, kl, base + 64, kr1);
        size_t cdst = ((((size_t)phys * 2 + 0) * HH + hh) * PBS + off) * DHE + j;
        cache[cdst]      = kr0;
        cache[cdst + 64] = kr1;
    }
    for (int i = tid; i < 2048; i += 256) {
        int hh = i >> 7, d = i & 127;
        float v = row[2 * DD + i];
        vh[(size_t)t * DD + i] = __float2half_rn(v);
        cache[((((size_t)phys * 2 + 1) * HH + hh) * PBS + off) * DHE + d] = v;
    }
}

// ============================================================
// Flash attention on mma.sync, fp16: QK 3-term split, PV 2-term
// (P split, V single). CTA: 128 q rows x 1 head x 1 batch.
// Epilogue writes the fp16 hi/lo split of attn output directly.
// ============================================================
#define AQT   128
#define AKT   64
#define AROWB 272                 // 128 fp16 (256B) + 16B pad
#define SM_QHI 0
#define SM_QLO (128 * AROWB)      // 34816
#define SM_KV0 (2 * 128 * AROWB)  // 69632
#define MATKV  (64 * AROWB)       // 17408: Khi | Klo | V
#define KVSTG  (3 * MATKV)        // 52224
#define ASMEM  (SM_KV0 + 2 * KVSTG)  // 174080
#define QK_SCALE 0.08838834764831843f   // 1/sqrt(128)

__device__ __forceinline__ uint32_t packsplit(float a, float b, uint32_t &lo) {
    __half ha = __float2half_rn(a), hb = __float2half_rn(b);
    __half2 l2 = __floats2half2_rn(a - __half2float(ha), b - __half2float(hb));
    lo = *(uint32_t*)&l2;
    __half2 h2;
    h2.x = ha; h2.y = hb;
    return *(uint32_t*)&h2;
}

__device__ __forceinline__ void attn_load_kv(
    uint32_t st, const __half* kh, const __half* kl, const __half* vh,
    int kbase, size_t hoff, int tid)
{
    for (int i = tid; i < 1024; i += 256) {      // 64 rows x 16 segs
        int r = i >> 4, seg = (i & 15) * 16;
        size_t grow = (size_t)(kbase + r) * DD + hoff;
        uint32_t d = st + r * AROWB + seg;
        cpa16(d,             (const char*)(kh + grow) + seg);
        cpa16(d + MATKV,     (const char*)(kl + grow) + seg);
        cpa16(d + 2 * MATKV, (const char*)(vh + grow) + seg);
    }
    CP_COMMIT();
}

__global__ __launch_bounds__(256, 1)
void attn_mma(const __half* __restrict__ qh, const __half* __restrict__ ql,
              const __half* __restrict__ kh, const __half* __restrict__ kl,
              const __half* __restrict__ vh,
              __half* __restrict__ oh, __half* __restrict__ ol) {
    extern __shared__ __align__(1024) uint8_t smem[];
    uint32_t sb = smem_to_u32(smem);
    int tid  = threadIdx.x;
    int wid  = tid >> 5, lane = tid & 31;
    int g    = lane >> 2, tq = lane & 3;
    int qt   = (gridDim.x - 1) - blockIdx.x;      // big tiles first
    int h    = blockIdx.y, b = blockIdx.z;
    int qbase = b * SS + qt * AQT;
    size_t hoff = (size_t)h * DHE;

    // load Q hi/lo tile (128 rows x 256B each)
    for (int i = tid; i < 2048; i += 256) {
        int r = i >> 4, seg = (i & 15) * 16;
        size_t grow = (size_t)(qbase + r) * DD + hoff;
        cpa16(sb + SM_QHI + r * AROWB + seg, (const char*)(qh + grow) + seg);
        cpa16(sb + SM_QLO + r * AROWB + seg, (const char*)(ql + grow) + seg);
    }
    // prefetch kt=0 (same commit group as Q)
    attn_load_kv(sb + SM_KV0, kh, kl, vh, b * SS, hoff, tid);

    float Oa[16][4];
#pragma unroll
    for (int i = 0; i < 16; i++)
#pragma unroll
        for (int j = 0; j < 4; j++) Oa[i][j] = 0.f;
    float m0v = -1e30f, m1v = -1e30f, l0 = 0.f, l1 = 0.f;
    int row0 = qt * AQT + wid * 16 + g;          // seq-local q position
    int ktmax = 2 * qt + 1;
    int lrow = lane & 15, lc16 = (lane >> 4) * 16;

    for (int kt = 0; kt <= ktmax; kt++) {
        int s = kt & 1;
        __syncthreads();                         // stage s^1 free for reuse
        if (kt < ktmax) {
            attn_load_kv(sb + SM_KV0 + (s ^ 1) * KVSTG, kh, kl, vh,
                         b * SS + (kt + 1) * AKT, hoff, tid);
            CP_WAIT(1);
        } else {
            CP_WAIT(0);
        }
        __syncthreads();

        uint32_t kvs = sb + SM_KV0 + s * KVSTG;

        // ---- scores S = Q K^T (3-term split) ----
        float sacc[8][4];
#pragma unroll
        for (int i = 0; i < 8; i++)
#pragma unroll
            for (int j = 0; j < 4; j++) sacc[i][j] = 0.f;

#pragma unroll
        for (int kc = 0; kc < 8; kc++) {
            uint32_t qa = sb + SM_QHI + (uint32_t)((wid * 16 + lrow) * AROWB + kc * 32 + lc16);
            uint32_t qhif[4], qlof[4];
            ldsm4(qhif[0], qhif[1], qhif[2], qhif[3], qa);
            ldsm4(qlof[0], qlof[1], qlof[2], qlof[3], qa + (SM_QLO - SM_QHI));
#pragma unroll
            for (int nf2 = 0; nf2 < 4; nf2++) {
                uint32_t ka = kvs + (uint32_t)((nf2 * 16 + lrow) * AROWB + kc * 32 + lc16);
                uint32_t t0, t1, t2, t3, u0, u1, u2, u3;
                ldsm4(t0, t1, t2, t3, ka);              // K hi
                ldsm4(u0, u1, u2, u3, ka + MATKV);      // K lo
                uint32_t bh0[2] = {t0, t2}, bh1[2] = {t1, t3};
                uint32_t bl0[2] = {u0, u2}, bl1[2] = {u1, u3};
                mma16816(sacc[2*nf2],   qhif, bh0);
                mma16816(sacc[2*nf2],   qlof, bh0);
                mma16816(sacc[2*nf2],   qhif, bl0);
                mma16816(sacc[2*nf2+1], qhif, bh1);
                mma16816(sacc[2*nf2+1], qlof, bh1);
                mma16816(sacc[2*nf2+1], qhif, bl1);
            }
        }

        // ---- causal mask (only diagonal tiles) ----
        if (kt >= 2 * qt) {
            int colb = kt * AKT + tq * 2;
#pragma unroll
            for (int nf = 0; nf < 8; nf++) {
                int c0 = colb + nf * 8, c1 = c0 + 1;
                if (c0 > row0)     sacc[nf][0] = -1e30f;
                if (c1 > row0)     sacc[nf][1] = -1e30f;
                if (c0 > row0 + 8) sacc[nf][2] = -1e30f;
                if (c1 > row0 + 8) sacc[nf][3] = -1e30f;
            }
        }

        // ---- online softmax ----
        float mx0 = -1e30f, mx1 = -1e30f;
#pragma unroll
        for (int nf = 0; nf < 8; nf++) {
            mx0 = fmaxf(mx0, fmaxf(sacc[nf][0], sacc[nf][1]));
            mx1 = fmaxf(mx1, fmaxf(sacc[nf][2], sacc[nf][3]));
        }
        mx0 = fmaxf(mx0, __shfl_xor_sync(0xffffffffu, mx0, 1));
        mx0 = fmaxf(mx0, __shfl_xor_sync(0xffffffffu, mx0, 2));
        mx1 = fmaxf(mx1, __shfl_xor_sync(0xffffffffu, mx1, 1));
        mx1 = fmaxf(mx1, __shfl_xor_sync(0xffffffffu, mx1, 2));
        float mn0 = fmaxf(m0v, mx0), mn1 = fmaxf(m1v, mx1);
        float al0 = __expf(QK_SCALE * (m0v - mn0));
        float al1 = __expf(QK_SCALE * (m1v - mn1));
        m0v = mn0; m1v = mn1;

        float sum0 = 0.f, sum1 = 0.f;
        uint32_t phi[4][4], plo[4][4];
#pragma unroll
        for (int kc = 0; kc < 4; kc++) {
            float p00 = __expf(QK_SCALE * (sacc[2*kc][0]   - mn0));
            float p01 = __expf(QK_SCALE * (sacc[2*kc][1]   - mn0));
            float p02 = __expf(QK_SCALE * (sacc[2*kc][2]   - mn1));
            float p03 = __expf(QK_SCALE * (sacc[2*kc][3]   - mn1));
            float p10 = __expf(QK_SCALE * (sacc[2*kc+1][0] - mn0));
            float p11 = __expf(QK_SCALE * (sacc[2*kc+1][1] - mn0));
            float p12 = __expf(QK_SCALE * (sacc[2*kc+1][2] - mn1));
            float p13 = __expf(QK_SCALE * (sacc[2*kc+1][3] - mn1));
            sum0 += (p00 + p01) + (p10 + p11);
            sum1 += (p02 + p03) + (p12 + p13);
            phi[kc][0] = packsplit(p00, p01, plo[kc][0]);
            phi[kc][1] = packsplit(p02, p03, plo[kc][1]);
            phi[kc][2] = packsplit(p10, p11, plo[kc][2]);
            phi[kc][3] = packsplit(p12, p13, plo[kc][3]);
        }
        sum0 += __shfl_xor_sync(0xffffffffu, sum0, 1);
        sum0 += __shfl_xor_sync(0xffffffffu, sum0, 2);
        sum1 += __shfl_xor_sync(0xffffffffu, sum1, 1);
        sum1 += __shfl_xor_sync(0xffffffffu, sum1, 2);
        l0 = l0 * al0 + sum0;
        l1 = l1 * al1 + sum1;
#pragma unroll
        for (int nf = 0; nf < 16; nf++) {
            Oa[nf][0] *= al0; Oa[nf][1] *= al0;
            Oa[nf][2] *= al1; Oa[nf][3] *= al1;
        }

        // ---- O += P V (2-term: P split, V single; ldmatrix.trans) ----
#pragma unroll
        for (int kc = 0; kc < 4; kc++) {
#pragma unroll
            for (int nf2 = 0; nf2 < 8; nf2++) {
                uint32_t va = kvs + 2 * MATKV +
                              (uint32_t)((kc * 16 + lrow) * AROWB + nf2 * 32 + lc16);
                uint32_t t0, t1, t2, t3;
                ldsm4t(t0, t1, t2, t3, va);
                uint32_t bh0[2] = {t0, t1}, bh1[2] = {t2, t3};
                mma16816(Oa[2*nf2],   phi[kc], bh0);
                mma16816(Oa[2*nf2],   plo[kc], bh0);
                mma16816(Oa[2*nf2+1], phi[kc], bh1);
                mma16816(Oa[2*nf2+1], plo[kc], bh1);
            }
        }
    }

    // ---- epilogue: write fp16 hi/lo split directly ----
    float il0 = 1.f / l0, il1 = 1.f / l1;
    size_t r0off = (size_t)(qbase + wid * 16 + g) * DD + hoff;
    size_t r1off = r0off + 8 * DD;
#pragma unroll
    for (int nf = 0; nf < 16; nf++) {
        int c = nf * 8 + tq * 2;
        uint32_t lo0, lo1;
        uint32_t hi0 = packsplit(Oa[nf][0] * il0, Oa[nf][1] * il0, lo0);
        uint32_t hi1 = packsplit(Oa[nf][2] * il1, Oa[nf][3] * il1, lo1);
        *(uint32_t*)(oh + r0off + c) = hi0;
        *(uint32_t*)(ol + r0off + c) = lo0;
        *(uint32_t*)(oh + r1off + c) = hi1;
        *(uint32_t*)(ol + r1off + c) = lo1;
    }
}

// ============================================================
// Launch
// ============================================================
extern "C" void kernel_launch(void* const* d_in, const int* in_sizes, int n_in,
                              void* d_out, int out_size) {
    (void)in_sizes; (void)n_in; (void)out_size;
    const float* x      = (const float*)d_in[0];
    const float* Wq     = (const float*)d_in[1];
    const float* Wk     = (const float*)d_in[2];
    const float* Wv     = (const float*)d_in[3];
    const float* Wo     = (const float*)d_in[4];
    const float* kv_in  = (const float*)d_in[5];
    const int*   btab   = (const int*)d_in[7];

    float* out       = (float*)d_out;
    float* cache_out = out + (size_t)TT * DD;

    void* p;
    cudaGetSymbolAddress(&p, g_qkv);     float*  qkv = (float*)p;
    cudaGetSymbolAddress(&p, g_ah);      __half* ah  = (__half*)p;
    cudaGetSymbolAddress(&p, g_al);      __half* al  = (__half*)p;
    cudaGetSymbolAddress(&p, g_wh);      __half* wh  = (__half*)p;
    cudaGetSymbolAddress(&p, g_qh);      __half* qh  = (__half*)p;
    cudaGetSymbolAddress(&p, g_ql);      __half* ql  = (__half*)p;
    cudaGetSymbolAddress(&p, g_kh);      __half* kh  = (__half*)p;
    cudaGetSymbolAddress(&p, g_kl);      __half* kl  = (__half*)p;
    cudaGetSymbolAddress(&p, g_vh);      __half* vh  = (__half*)p;
    cudaGetSymbolAddress(&p, g_ropetab); float2* rtab = (float2*)p;

    cudaFuncSetAttribute(gemm_mma, cudaFuncAttributeMaxDynamicSharedMemorySize, GEMM_SMEM);
    cudaFuncSetAttribute(attn_mma, cudaFuncAttributeMaxDynamicSharedMemorySize, ASMEM);

    // copy input cache (untouched blocks must survive), then scatter overwrites
    cudaMemcpyAsync(cache_out, kv_in,
                    (size_t)NBLK * 2 * HH * PBS * DHE * sizeof(float),
                    cudaMemcpyDeviceToDevice, 0);

    const int nx4 = TT * DD / 4, nw4 = DD * DD / 4;

    // fused QKV projection: one N=6144 GEMM against concatenated fp16 weights
    split_half<<<(nx4 + 255) / 256, 256>>>((const float4*)x, (ushort4*)ah, (ushort4*)al, nx4);
    to_half<<<(nw4 + 255) / 256, 256>>>((const float4*)Wq, (ushort4*)(wh), nw4);
    to_half<<<(nw4 + 255) / 256, 256>>>((const float4*)Wk, (ushort4*)(wh + (size_t)DD * DD), nw4);
    to_half<<<(nw4 + 255) / 256, 256>>>((const float4*)Wv, (ushort4*)(wh + 2 * (size_t)DD * DD), nw4);
    gemm_mma<<<dim3(3 * DD / GBN, TT / GBM), 256, GEMM_SMEM>>>(ah, al, wh, qkv, 3 * DD);

    // fused RoPE + fp16 split + paged KV scatter
    rope_table<<<256, 256>>>(rtab);
    rope_split_scatter<<<TT, 256>>>(qkv, btab, rtab, qh, ql, kh, kl, vh, cache_out);

    // Wo -> fp16 (reuses wh after QKV GEMM; stream-ordered)
    to_half<<<(nw4 + 255) / 256, 256>>>((const float4*)Wo, (ushort4*)wh, nw4);

    // attention (epilogue writes split fp16 into ah/al)
    attn_mma<<<dim3(SS / AQT, HH, BBQ), 256, ASMEM>>>(qh, ql, kh, kl, vh, ah, al);

    // output projection
    gemm_mma<<<dim3(DD / GBN, TT / GBM), 256, GEMM_SMEM>>>(ah, al, wh, out, DD);
}